// round 1
// baseline (speedup 1.0000x reference)
#include <cuda_runtime.h>
#include <math.h>

#define BB 16
#define LL 512
#define DD 768
#define HOPS 3
#define NH (HOPS + 1)

// ---------------- scratch (static device globals; no allocs) ----------------
__device__ __align__(16) float g_xpad[(long)BB * (LL + 2) * DD];   // padded cur for conv
__device__ __align__(16) float g_conv[(long)BB * LL * DD];         // conv output / cur
__device__ __align__(16) float g_norm[(long)BB * LL * DD];         // l2-normalized conv
__device__ __align__(16) float g_scores[(long)BB * LL * LL];       // attention matrix
__device__ __align__(16) float g_result[(long)BB * LL * NH * DD];  // [B,L,4,D]
__device__ __align__(16) float g_hidden[(long)BB * LL * NH * DD];  // tanh(result@W1+b1)
__device__ __align__(16) float g_wt[(long)HOPS * 3 * DD * DD];     // conv weights, K-major

// ---------------- generic 128x128x16 SGEMM ----------------
// C[M,N] = A[M,K] * B  (+ epilogue)
// BT=true : B is [N,K] row-major (NT gemm)
// BT=false: B is [K,N] row-major (NN gemm)
// EPI: 0 none, 1 relu(x+bias[n]), 2 tanh(x+bias[n])
template <bool BT, int EPI>
__global__ __launch_bounds__(256) void gemm128(
    const float* __restrict__ A, const float* __restrict__ Bm,
    float* __restrict__ C, const float* __restrict__ bias,
    int K, int lda, int ldb, int ldc,
    long sA, long sB, long sC)
{
    constexpr int BM = 128, BN = 128, BK = 16;
    __shared__ float As[BK][BM + 4];
    __shared__ float Bs[BK][BN + 4];

    const int tid = threadIdx.x;
    const int bx = blockIdx.x, by = blockIdx.y, bz = blockIdx.z;

    const float* Ab = A + (long)bz * sA + (long)by * BM * lda;
    const float* Bb;
    if (BT) Bb = Bm + (long)bz * sB + (long)bx * BN * ldb;
    else    Bb = Bm + (long)bz * sB + bx * BN;

    const int tx = tid & 15;       // N direction
    const int ty = tid >> 4;       // M direction

    float acc[8][8];
#pragma unroll
    for (int i = 0; i < 8; i++)
#pragma unroll
        for (int j = 0; j < 8; j++) acc[i][j] = 0.f;

    for (int k0 = 0; k0 < K; k0 += BK) {
        // A tile: 128 rows x 16 cols -> As[k][m] (transposed store)
#pragma unroll
        for (int t = 0; t < 2; t++) {
            int id  = tid + t * 256;
            int row = id >> 2;
            int c4  = (id & 3) * 4;
            float4 v = *reinterpret_cast<const float4*>(Ab + (long)row * lda + k0 + c4);
            As[c4 + 0][row] = v.x; As[c4 + 1][row] = v.y;
            As[c4 + 2][row] = v.z; As[c4 + 3][row] = v.w;
        }
        if (BT) {
#pragma unroll
            for (int t = 0; t < 2; t++) {
                int id  = tid + t * 256;
                int row = id >> 2;
                int c4  = (id & 3) * 4;
                float4 v = *reinterpret_cast<const float4*>(Bb + (long)row * ldb + k0 + c4);
                Bs[c4 + 0][row] = v.x; Bs[c4 + 1][row] = v.y;
                Bs[c4 + 2][row] = v.z; Bs[c4 + 3][row] = v.w;
            }
        } else {
#pragma unroll
            for (int t = 0; t < 2; t++) {
                int id  = tid + t * 256;
                int row = id >> 5;          // 0..15 (k)
                int c4  = (id & 31) * 4;    // 0..124 (n)
                float4 v = *reinterpret_cast<const float4*>(Bb + (long)(k0 + row) * ldb + c4);
                *reinterpret_cast<float4*>(&Bs[row][c4]) = v;
            }
        }
        __syncthreads();

#pragma unroll
        for (int kk = 0; kk < BK; kk++) {
            float a[8], b[8];
#pragma unroll
            for (int i = 0; i < 8; i++) a[i] = As[kk][ty * 8 + i];
#pragma unroll
            for (int j = 0; j < 8; j++) b[j] = Bs[kk][tx * 8 + j];
#pragma unroll
            for (int i = 0; i < 8; i++)
#pragma unroll
                for (int j = 0; j < 8; j++) acc[i][j] += a[i] * b[j];
        }
        __syncthreads();
    }

    float* Cb = C + (long)bz * sC + (long)(by * BM) * ldc + bx * BN;
    float bcol[8];
    if (EPI != 0) {
#pragma unroll
        for (int j = 0; j < 8; j++) bcol[j] = bias[bx * BN + tx * 8 + j];
    }
#pragma unroll
    for (int i = 0; i < 8; i++) {
        int m = ty * 8 + i;
        float4 v0, v1;
        float vv[8];
#pragma unroll
        for (int j = 0; j < 8; j++) {
            float v = acc[i][j];
            if (EPI == 1) v = fmaxf(v + bcol[j], 0.f);
            else if (EPI == 2) v = tanhf(v + bcol[j]);
            vv[j] = v;
        }
        v0 = make_float4(vv[0], vv[1], vv[2], vv[3]);
        v1 = make_float4(vv[4], vv[5], vv[6], vv[7]);
        *reinterpret_cast<float4*>(Cb + (long)m * ldc + tx * 8)     = v0;
        *reinterpret_cast<float4*>(Cb + (long)m * ldc + tx * 8 + 4) = v1;
    }
}

// ---------------- masked-softmax over rows of [B,L,L] (one warp per row) ----
__global__ void softmask_kernel(float* __restrict__ S, const float* __restrict__ mask)
{
    int gw   = (blockIdx.x * blockDim.x + threadIdx.x) >> 5;
    int lane = threadIdx.x & 31;
    if (gw >= BB * LL) return;
    int b = gw / LL;
    int l = gw - b * LL;
    float* row = S + (long)gw * LL;
    const float* mk = mask + (long)b * LL;

    float v[16];
    float mx = -1e30f;
#pragma unroll
    for (int t = 0; t < 16; t++) {
        v[t] = row[lane + t * 32];
        mx = fmaxf(mx, v[t]);
    }
#pragma unroll
    for (int o = 16; o; o >>= 1) mx = fmaxf(mx, __shfl_xor_sync(0xffffffffu, mx, o));

    float sum = 0.f;
#pragma unroll
    for (int t = 0; t < 16; t++) {
        float e = __expf(v[t] - mx) * mk[lane + t * 32];
        v[t] = e;
        sum += e;
    }
#pragma unroll
    for (int o = 16; o; o >>= 1) sum += __shfl_xor_sync(0xffffffffu, sum, o);

    float scale = mk[l] / (sum + 1e-10f);   // query mask folded into the scale
#pragma unroll
    for (int t = 0; t < 16; t++) row[lane + t * 32] = v[t] * scale;
}

// ---------------- L2 normalize rows of [B*L, D] (one warp per row) ----------
__global__ void l2norm_kernel(const float* __restrict__ X, float* __restrict__ Y)
{
    int gw   = (blockIdx.x * blockDim.x + threadIdx.x) >> 5;
    int lane = threadIdx.x & 31;
    if (gw >= BB * LL) return;
    const float* x = X + (long)gw * DD;
    float* y = Y + (long)gw * DD;
    float ss = 0.f;
#pragma unroll
    for (int t = 0; t < 24; t++) {
        float v = x[lane + t * 32];
        ss += v * v;
    }
#pragma unroll
    for (int o = 16; o; o >>= 1) ss += __shfl_xor_sync(0xffffffffu, ss, o);
    float scale = 1.f / fmaxf(sqrtf(ss), 1e-12f);
#pragma unroll
    for (int t = 0; t < 24; t++) y[lane + t * 32] = x[lane + t * 32] * scale;
}

// ---------------- build zero-padded cur for conv ----------------------------
__global__ void pad_kernel(const float* __restrict__ X)
{
    const int n = BB * (LL + 2) * DD;
    for (int i = blockIdx.x * blockDim.x + threadIdx.x; i < n;
         i += gridDim.x * blockDim.x) {
        int bi = i / ((LL + 2) * DD);
        int r  = (i / DD) % (LL + 2);
        int d  = i % DD;
        float v = 0.f;
        if (r >= 1 && r <= LL) v = X[((long)bi * LL + (r - 1)) * DD + d];
        g_xpad[i] = v;
    }
}

// ---------------- conv weight transpose: W[h][o][i][k] -> Wt[h][k*D+i][o] ---
__global__ void wtrans_kernel(const float* __restrict__ W)
{
    const long n = (long)HOPS * 3 * DD * DD;
    for (long i = blockIdx.x * (long)blockDim.x + threadIdx.x; i < n;
         i += (long)gridDim.x * blockDim.x) {
        long h    = i / (3L * DD * DD);
        long rem  = i - h * 3L * DD * DD;
        long k    = rem / ((long)DD * DD);
        long rem2 = rem - k * (long)DD * DD;
        long ii   = rem2 / DD;
        long o    = rem2 - ii * DD;
        g_wt[i] = W[((h * DD + o) * DD + ii) * 3 + k];
    }
}

// ---------------- pooling tail: scores, softmax over hops, weighted sum -----
__global__ void pool_finalize_kernel(const float* __restrict__ w2,
                                     const float* __restrict__ b2,
                                     float* __restrict__ out)
{
    int gw   = (blockIdx.x * blockDim.x + threadIdx.x) >> 5;
    int lane = threadIdx.x & 31;
    if (gw >= BB * LL) return;
    const float* hid = g_hidden + (long)gw * NH * DD;
    const float* res = g_result + (long)gw * NH * DD;

    float s[NH];
#pragma unroll
    for (int h = 0; h < NH; h++) {
        float dot = 0.f;
#pragma unroll
        for (int t = 0; t < 24; t++) {
            int d = lane + t * 32;
            dot += hid[h * DD + d] * w2[d];
        }
#pragma unroll
        for (int o = 16; o; o >>= 1) dot += __shfl_xor_sync(0xffffffffu, dot, o);
        s[h] = dot + b2[0];
    }
    float mx = fmaxf(fmaxf(s[0], s[1]), fmaxf(s[2], s[3]));
    float e0 = __expf(s[0] - mx), e1 = __expf(s[1] - mx);
    float e2 = __expf(s[2] - mx), e3 = __expf(s[3] - mx);
    float inv = 1.f / (e0 + e1 + e2 + e3);
    e0 *= inv; e1 *= inv; e2 *= inv; e3 *= inv;

    float* o = out + (long)gw * DD;
#pragma unroll
    for (int t = 0; t < 24; t++) {
        int d = lane + t * 32;
        o[d] = e0 * res[d] + e1 * res[DD + d] + e2 * res[2 * DD + d] + e3 * res[3 * DD + d];
    }
}

__global__ void copy_kernel(const float* __restrict__ src, float* __restrict__ dst, int n)
{
    for (int i = blockIdx.x * blockDim.x + threadIdx.x; i < n;
         i += gridDim.x * blockDim.x) dst[i] = src[i];
}

// ---------------- orchestration ---------------------------------------------
extern "C" void kernel_launch(void* const* d_in, const int* in_sizes, int n_in,
                              void* d_out, int out_size)
{
    (void)in_sizes; (void)n_in; (void)out_size;
    const float* inputs  = (const float*)d_in[0];
    const float* mask    = (const float*)d_in[1];
    const float* conv_w  = (const float*)d_in[2];
    const float* conv_b  = (const float*)d_in[3];
    const float* pool_w1 = (const float*)d_in[4];
    const float* pool_b1 = (const float*)d_in[5];
    const float* pool_w2 = (const float*)d_in[6];
    const float* pool_b2 = (const float*)d_in[7];
    float* out = (float*)d_out;

    float *xpad, *conv, *nrm, *scores, *result, *hidden, *wt;
    cudaGetSymbolAddress((void**)&xpad,   g_xpad);
    cudaGetSymbolAddress((void**)&conv,   g_conv);
    cudaGetSymbolAddress((void**)&nrm,    g_norm);
    cudaGetSymbolAddress((void**)&scores, g_scores);
    cudaGetSymbolAddress((void**)&result, g_result);
    cudaGetSymbolAddress((void**)&hidden, g_hidden);
    cudaGetSymbolAddress((void**)&wt,     g_wt);

    // conv weights -> K-major [3D, D] per hop
    wtrans_kernel<<<256, 256>>>(conv_w);

    // ---- hop 0: raw similarity on inputs ----
    gemm128<true, 0><<<dim3(LL / 128, LL / 128, BB), 256>>>(
        inputs, inputs, scores, nullptr,
        DD, DD, DD, LL, (long)LL * DD, (long)LL * DD, (long)LL * LL);
    softmask_kernel<<<BB * LL / 8, 256>>>(scores, mask);
    gemm128<false, 0><<<dim3(DD / 128, LL / 128, BB), 256>>>(
        scores, inputs, result /* hop 0 slot */, nullptr,
        LL, LL, DD, NH * DD, (long)LL * LL, (long)LL * DD, (long)LL * NH * DD);

    // ---- hops 1..3 ----
    const float* cur = inputs;
    for (int h = 0; h < HOPS; h++) {
        pad_kernel<<<1024, 256>>>(cur);
        // conv1d as implicit-im2col NN GEMM: A rows are 3*D contiguous floats of xpad
        gemm128<false, 1><<<dim3(DD / 128, LL / 128, BB), 256>>>(
            xpad, wt + (long)h * 3 * DD * DD, conv, conv_b + h * DD,
            3 * DD, DD, DD, DD, (long)(LL + 2) * DD, 0L, (long)LL * DD);
        l2norm_kernel<<<BB * LL / 8, 256>>>(conv, nrm);
        gemm128<true, 0><<<dim3(LL / 128, LL / 128, BB), 256>>>(
            nrm, nrm, scores, nullptr,
            DD, DD, DD, LL, (long)LL * DD, (long)LL * DD, (long)LL * LL);
        softmask_kernel<<<BB * LL / 8, 256>>>(scores, mask);
        gemm128<false, 0><<<dim3(DD / 128, LL / 128, BB), 256>>>(
            scores, conv, result + (long)(h + 1) * DD, nullptr,
            LL, LL, DD, NH * DD, (long)LL * LL, (long)LL * DD, (long)LL * NH * DD);
        cur = conv;
    }

    // output #1: cur
    copy_kernel<<<1024, 256>>>(conv, out, BB * LL * DD);

    // pooling: hidden = tanh(result @ W1 + b1), one big NN GEMM (M = B*L*4)
    gemm128<false, 2><<<dim3(DD / 128, (BB * LL * NH) / 128, 1), 256>>>(
        result, pool_w1, hidden, pool_b1,
        DD, DD, DD, DD, 0L, 0L, 0L);

    // output #2: weighted
    pool_finalize_kernel<<<BB * LL / 8, 256>>>(pool_w2, pool_b2, out + (long)BB * LL * DD);
}

// round 2
// speedup vs baseline: 2.2944x; 2.2944x over previous
#include <cuda_runtime.h>
#include <math.h>

#define BB 16
#define LL 512
#define DD 768
#define HOPS 3
#define NH (HOPS + 1)

// ---------------- scratch (static device globals; no allocs) ----------------
__device__ __align__(16) float g_xpad[(long)BB * (LL + 2) * DD];   // padded cur for conv
__device__ __align__(16) float g_conv[(long)BB * LL * DD];         // conv output / cur
__device__ __align__(16) float g_norm[(long)BB * LL * DD];         // l2-normalized conv
__device__ __align__(16) float g_scores[(long)BB * LL * LL];       // attention matrix
__device__ __align__(16) float g_result[(long)BB * LL * NH * DD];  // [B,L,4,D]
__device__ __align__(16) float g_hidden[(long)BB * LL * NH * DD];  // tanh(result@W1+b1)
__device__ __align__(16) float g_wt[(long)HOPS * 3 * DD * DD];     // conv weights, K-major

// ---- fp32 -> tf32 with round-to-nearest (bias-free; truncation would add
//      a coherent ~4e-3 relative bias on K=768 dot products) ----
__device__ __forceinline__ float f2tf32(float x) {
    unsigned y;
    asm("cvt.rna.tf32.f32 %0, %1;" : "=r"(y) : "f"(x));
    return __uint_as_float(y);
}

__device__ __forceinline__ void mma_tf32(float c[4],
                                         unsigned a0, unsigned a1, unsigned a2, unsigned a3,
                                         unsigned b0, unsigned b1) {
    asm volatile(
        "mma.sync.aligned.m16n8k8.row.col.f32.tf32.tf32.f32 "
        "{%0,%1,%2,%3}, {%4,%5,%6,%7}, {%8,%9}, {%0,%1,%2,%3};"
        : "+f"(c[0]), "+f"(c[1]), "+f"(c[2]), "+f"(c[3])
        : "r"(a0), "r"(a1), "r"(a2), "r"(a3), "r"(b0), "r"(b1));
}

// ---------------- tensor-core 128x128x16 GEMM (tf32, fp32 accum) -----------
// C[M,N] = A[M,K] * B  (+ epilogue)
// BT=true : B is [N,K] row-major (NT gemm)
// BT=false: B is [K,N] row-major (NN gemm)
// EPI: 0 none, 1 relu(x+bias[n]), 2 tanh(x+bias[n])
template <bool BT, int EPI>
__global__ __launch_bounds__(256, 2) void gemm_tc(
    const float* __restrict__ A, const float* __restrict__ Bm,
    float* __restrict__ C, const float* __restrict__ bias,
    int K, int lda, int ldb, int ldc,
    long sA, long sB, long sC)
{
    constexpr int BM = 128, BN = 128, BK = 16;
    __shared__ float As[BK][BM + 8];
    __shared__ float Bs[BK][BN + 8];

    const int tid = threadIdx.x;
    const int bx = blockIdx.x, by = blockIdx.y, bz = blockIdx.z;

    const float* Ab = A + (long)bz * sA + (long)by * BM * lda;
    const float* Bb;
    if (BT) Bb = Bm + (long)bz * sB + (long)bx * BN * ldb;
    else    Bb = Bm + (long)bz * sB + bx * BN;

    const int wid  = tid >> 5;
    const int lane = tid & 31;
    const int wm = (wid & 1) * 64;   // warp row base (2 warps in M)
    const int wn = (wid >> 1) * 32;  // warp col base (4 warps in N)
    const int gid = lane >> 2;       // 0..7
    const int tig = lane & 3;        // 0..3

    float acc[4][4][4];
#pragma unroll
    for (int mt = 0; mt < 4; mt++)
#pragma unroll
        for (int nt = 0; nt < 4; nt++)
#pragma unroll
            for (int r = 0; r < 4; r++) acc[mt][nt][r] = 0.f;

    float4 ra[2], rb[2];

    auto ldg_tile = [&](int k0) {
#pragma unroll
        for (int t = 0; t < 2; t++) {
            int id = tid + t * 256;
            int row = id >> 2;
            int c4 = (id & 3) * 4;
            ra[t] = *reinterpret_cast<const float4*>(Ab + (long)row * lda + k0 + c4);
        }
        if (BT) {
#pragma unroll
            for (int t = 0; t < 2; t++) {
                int id = tid + t * 256;
                int row = id >> 2;
                int c4 = (id & 3) * 4;
                rb[t] = *reinterpret_cast<const float4*>(Bb + (long)row * ldb + k0 + c4);
            }
        } else {
#pragma unroll
            for (int t = 0; t < 2; t++) {
                int id = tid + t * 256;
                int row = id >> 5;          // k (0..15)
                int c4 = (id & 31) * 4;     // n
                rb[t] = *reinterpret_cast<const float4*>(Bb + (long)(k0 + row) * ldb + c4);
            }
        }
    };

    auto sts_tile = [&]() {
#pragma unroll
        for (int t = 0; t < 2; t++) {
            int id = tid + t * 256;
            int row = id >> 2;
            int c4 = (id & 3) * 4;
            As[c4 + 0][row] = f2tf32(ra[t].x);
            As[c4 + 1][row] = f2tf32(ra[t].y);
            As[c4 + 2][row] = f2tf32(ra[t].z);
            As[c4 + 3][row] = f2tf32(ra[t].w);
        }
        if (BT) {
#pragma unroll
            for (int t = 0; t < 2; t++) {
                int id = tid + t * 256;
                int row = id >> 2;
                int c4 = (id & 3) * 4;
                Bs[c4 + 0][row] = f2tf32(rb[t].x);
                Bs[c4 + 1][row] = f2tf32(rb[t].y);
                Bs[c4 + 2][row] = f2tf32(rb[t].z);
                Bs[c4 + 3][row] = f2tf32(rb[t].w);
            }
        } else {
#pragma unroll
            for (int t = 0; t < 2; t++) {
                int id = tid + t * 256;
                int row = id >> 5;
                int c4 = (id & 31) * 4;
                Bs[row][c4 + 0] = f2tf32(rb[t].x);
                Bs[row][c4 + 1] = f2tf32(rb[t].y);
                Bs[row][c4 + 2] = f2tf32(rb[t].z);
                Bs[row][c4 + 3] = f2tf32(rb[t].w);
            }
        }
    };

    ldg_tile(0);
    for (int k0 = 0; k0 < K; k0 += BK) {
        sts_tile();
        __syncthreads();
        if (k0 + BK < K) ldg_tile(k0 + BK);

#pragma unroll
        for (int ks = 0; ks < BK; ks += 8) {
            unsigned bf[4][2];
#pragma unroll
            for (int nt = 0; nt < 4; nt++) {
                bf[nt][0] = __float_as_uint(Bs[ks + tig][wn + nt * 8 + gid]);
                bf[nt][1] = __float_as_uint(Bs[ks + tig + 4][wn + nt * 8 + gid]);
            }
#pragma unroll
            for (int mt = 0; mt < 4; mt++) {
                unsigned a0 = __float_as_uint(As[ks + tig][wm + mt * 16 + gid]);
                unsigned a1 = __float_as_uint(As[ks + tig][wm + mt * 16 + gid + 8]);
                unsigned a2 = __float_as_uint(As[ks + tig + 4][wm + mt * 16 + gid]);
                unsigned a3 = __float_as_uint(As[ks + tig + 4][wm + mt * 16 + gid + 8]);
#pragma unroll
                for (int nt = 0; nt < 4; nt++)
                    mma_tf32(acc[mt][nt], a0, a1, a2, a3, bf[nt][0], bf[nt][1]);
            }
        }
        __syncthreads();
    }

    float* Cb = C + (long)bz * sC + (long)(by * BM) * ldc + bx * BN;
#pragma unroll
    for (int nt = 0; nt < 4; nt++) {
        const int c = wn + nt * 8 + 2 * tig;
        float b0 = 0.f, b1 = 0.f;
        if (EPI != 0) {
            b0 = bias[bx * BN + c];
            b1 = bias[bx * BN + c + 1];
        }
#pragma unroll
        for (int mt = 0; mt < 4; mt++) {
            const int r0 = wm + mt * 16 + gid;
            float v0 = acc[mt][nt][0], v1 = acc[mt][nt][1];
            float v2 = acc[mt][nt][2], v3 = acc[mt][nt][3];
            if (EPI == 1) {
                v0 = fmaxf(v0 + b0, 0.f); v1 = fmaxf(v1 + b1, 0.f);
                v2 = fmaxf(v2 + b0, 0.f); v3 = fmaxf(v3 + b1, 0.f);
            } else if (EPI == 2) {
                v0 = tanhf(v0 + b0); v1 = tanhf(v1 + b1);
                v2 = tanhf(v2 + b0); v3 = tanhf(v3 + b1);
            }
            *reinterpret_cast<float2*>(Cb + (long)r0 * ldc + c)       = make_float2(v0, v1);
            *reinterpret_cast<float2*>(Cb + (long)(r0 + 8) * ldc + c) = make_float2(v2, v3);
        }
    }
}

// ---------------- masked-softmax over rows of [B,L,L] (one warp per row) ----
__global__ void softmask_kernel(float* __restrict__ S, const float* __restrict__ mask)
{
    int gw   = (blockIdx.x * blockDim.x + threadIdx.x) >> 5;
    int lane = threadIdx.x & 31;
    if (gw >= BB * LL) return;
    int b = gw / LL;
    int l = gw - b * LL;
    float* row = S + (long)gw * LL;
    const float* mk = mask + (long)b * LL;

    float v[16];
    float mx = -1e30f;
#pragma unroll
    for (int t = 0; t < 16; t++) {
        v[t] = row[lane + t * 32];
        mx = fmaxf(mx, v[t]);
    }
#pragma unroll
    for (int o = 16; o; o >>= 1) mx = fmaxf(mx, __shfl_xor_sync(0xffffffffu, mx, o));

    float sum = 0.f;
#pragma unroll
    for (int t = 0; t < 16; t++) {
        float e = __expf(v[t] - mx) * mk[lane + t * 32];
        v[t] = e;
        sum += e;
    }
#pragma unroll
    for (int o = 16; o; o >>= 1) sum += __shfl_xor_sync(0xffffffffu, sum, o);

    float scale = mk[l] / (sum + 1e-10f);   // query mask folded into the scale
#pragma unroll
    for (int t = 0; t < 16; t++) row[lane + t * 32] = v[t] * scale;
}

// ---------------- L2 normalize rows of [B*L, D] (one warp per row) ----------
__global__ void l2norm_kernel(const float* __restrict__ X, float* __restrict__ Y)
{
    int gw   = (blockIdx.x * blockDim.x + threadIdx.x) >> 5;
    int lane = threadIdx.x & 31;
    if (gw >= BB * LL) return;
    const float* x = X + (long)gw * DD;
    float* y = Y + (long)gw * DD;
    float ss = 0.f;
#pragma unroll
    for (int t = 0; t < 24; t++) {
        float v = x[lane + t * 32];
        ss += v * v;
    }
#pragma unroll
    for (int o = 16; o; o >>= 1) ss += __shfl_xor_sync(0xffffffffu, ss, o);
    float scale = 1.f / fmaxf(sqrtf(ss), 1e-12f);
#pragma unroll
    for (int t = 0; t < 24; t++) y[lane + t * 32] = x[lane + t * 32] * scale;
}

// ---------------- build zero-padded cur for conv ----------------------------
__global__ void pad_kernel(const float* __restrict__ X)
{
    const int n = BB * (LL + 2) * DD;
    for (int i = blockIdx.x * blockDim.x + threadIdx.x; i < n;
         i += gridDim.x * blockDim.x) {
        int bi = i / ((LL + 2) * DD);
        int r  = (i / DD) % (LL + 2);
        int d  = i % DD;
        float v = 0.f;
        if (r >= 1 && r <= LL) v = X[((long)bi * LL + (r - 1)) * DD + d];
        g_xpad[i] = v;
    }
}

// ---------------- conv weight transpose: W[h][o][i][k] -> Wt[h][k*D+i][o] ---
__global__ void wtrans_kernel(const float* __restrict__ W)
{
    const long n = (long)HOPS * 3 * DD * DD;
    for (long i = blockIdx.x * (long)blockDim.x + threadIdx.x; i < n;
         i += (long)gridDim.x * blockDim.x) {
        long h    = i / (3L * DD * DD);
        long rem  = i - h * 3L * DD * DD;
        long k    = rem / ((long)DD * DD);
        long rem2 = rem - k * (long)DD * DD;
        long ii   = rem2 / DD;
        long o    = rem2 - ii * DD;
        g_wt[i] = W[((h * DD + o) * DD + ii) * 3 + k];
    }
}

// ---------------- pooling tail: scores, softmax over hops, weighted sum -----
__global__ void pool_finalize_kernel(const float* __restrict__ w2,
                                     const float* __restrict__ b2,
                                     float* __restrict__ out)
{
    int gw   = (blockIdx.x * blockDim.x + threadIdx.x) >> 5;
    int lane = threadIdx.x & 31;
    if (gw >= BB * LL) return;
    const float* hid = g_hidden + (long)gw * NH * DD;
    const float* res = g_result + (long)gw * NH * DD;

    float s[NH];
#pragma unroll
    for (int h = 0; h < NH; h++) {
        float dot = 0.f;
#pragma unroll
        for (int t = 0; t < 24; t++) {
            int d = lane + t * 32;
            dot += hid[h * DD + d] * w2[d];
        }
#pragma unroll
        for (int o = 16; o; o >>= 1) dot += __shfl_xor_sync(0xffffffffu, dot, o);
        s[h] = dot + b2[0];
    }
    float mx = fmaxf(fmaxf(s[0], s[1]), fmaxf(s[2], s[3]));
    float e0 = __expf(s[0] - mx), e1 = __expf(s[1] - mx);
    float e2 = __expf(s[2] - mx), e3 = __expf(s[3] - mx);
    float inv = 1.f / (e0 + e1 + e2 + e3);
    e0 *= inv; e1 *= inv; e2 *= inv; e3 *= inv;

    float* o = out + (long)gw * DD;
#pragma unroll
    for (int t = 0; t < 24; t++) {
        int d = lane + t * 32;
        o[d] = e0 * res[d] + e1 * res[DD + d] + e2 * res[2 * DD + d] + e3 * res[3 * DD + d];
    }
}

__global__ void copy_kernel(const float* __restrict__ src, float* __restrict__ dst, int n)
{
    for (int i = blockIdx.x * blockDim.x + threadIdx.x; i * 4 < n;
         i += gridDim.x * blockDim.x) {
        *reinterpret_cast<float4*>(dst + i * 4) =
            *reinterpret_cast<const float4*>(src + i * 4);
    }
}

// ---------------- orchestration ---------------------------------------------
extern "C" void kernel_launch(void* const* d_in, const int* in_sizes, int n_in,
                              void* d_out, int out_size)
{
    (void)in_sizes; (void)n_in; (void)out_size;
    const float* inputs  = (const float*)d_in[0];
    const float* mask    = (const float*)d_in[1];
    const float* conv_w  = (const float*)d_in[2];
    const float* conv_b  = (const float*)d_in[3];
    const float* pool_w1 = (const float*)d_in[4];
    const float* pool_b1 = (const float*)d_in[5];
    const float* pool_w2 = (const float*)d_in[6];
    const float* pool_b2 = (const float*)d_in[7];
    float* out = (float*)d_out;

    float *xpad, *conv, *nrm, *scores, *result, *hidden, *wt;
    cudaGetSymbolAddress((void**)&xpad,   g_xpad);
    cudaGetSymbolAddress((void**)&conv,   g_conv);
    cudaGetSymbolAddress((void**)&nrm,    g_norm);
    cudaGetSymbolAddress((void**)&scores, g_scores);
    cudaGetSymbolAddress((void**)&result, g_result);
    cudaGetSymbolAddress((void**)&hidden, g_hidden);
    cudaGetSymbolAddress((void**)&wt,     g_wt);

    // conv weights -> K-major [3D, D] per hop
    wtrans_kernel<<<256, 256>>>(conv_w);

    // ---- hop 0: raw similarity on inputs ----
    gemm_tc<true, 0><<<dim3(LL / 128, LL / 128, BB), 256>>>(
        inputs, inputs, scores, nullptr,
        DD, DD, DD, LL, (long)LL * DD, (long)LL * DD, (long)LL * LL);
    softmask_kernel<<<BB * LL / 8, 256>>>(scores, mask);
    gemm_tc<false, 0><<<dim3(DD / 128, LL / 128, BB), 256>>>(
        scores, inputs, result /* hop 0 slot */, nullptr,
        LL, LL, DD, NH * DD, (long)LL * LL, (long)LL * DD, (long)LL * NH * DD);

    // ---- hops 1..3 ----
    const float* cur = inputs;
    for (int h = 0; h < HOPS; h++) {
        pad_kernel<<<1024, 256>>>(cur);
        // conv1d as implicit-im2col NN GEMM: A rows are 3*D contiguous floats of xpad
        gemm_tc<false, 1><<<dim3(DD / 128, LL / 128, BB), 256>>>(
            xpad, wt + (long)h * 3 * DD * DD, conv, conv_b + h * DD,
            3 * DD, DD, DD, DD, (long)(LL + 2) * DD, 0L, (long)LL * DD);
        l2norm_kernel<<<BB * LL / 8, 256>>>(conv, nrm);
        gemm_tc<true, 0><<<dim3(LL / 128, LL / 128, BB), 256>>>(
            nrm, nrm, scores, nullptr,
            DD, DD, DD, LL, (long)LL * DD, (long)LL * DD, (long)LL * LL);
        softmask_kernel<<<BB * LL / 8, 256>>>(scores, mask);
        gemm_tc<false, 0><<<dim3(DD / 128, LL / 128, BB), 256>>>(
            scores, conv, result + (long)(h + 1) * DD, nullptr,
            LL, LL, DD, NH * DD, (long)LL * LL, (long)LL * DD, (long)LL * NH * DD);
        cur = conv;
    }

    // output #1: cur
    copy_kernel<<<1024, 256>>>(conv, out, BB * LL * DD);

    // pooling: hidden = tanh(result @ W1 + b1), one big NN GEMM (M = B*L*4)
    gemm_tc<false, 2><<<dim3(DD / 128, (BB * LL * NH) / 128, 1), 256>>>(
        result, pool_w1, hidden, pool_b1,
        DD, DD, DD, DD, 0L, 0L, 0L);

    // output #2: weighted
    pool_finalize_kernel<<<BB * LL / 8, 256>>>(pool_w2, pool_b2, out + (long)BB * LL * DD);
}

// round 3
// speedup vs baseline: 2.8421x; 1.2387x over previous
#include <cuda_runtime.h>
#include <math.h>

#define BB 16
#define LL 512
#define DD 768
#define HOPS 3
#define NH (HOPS + 1)

// ---------------- scratch (static device globals; no allocs) ----------------
__device__ __align__(16) float g_xpad[(long)BB * (LL + 2) * DD];   // padded cur (tf32-rounded)
__device__ __align__(16) float g_conv[(long)BB * LL * DD];         // conv output fp32
__device__ __align__(16) float g_convr[(long)BB * LL * DD];        // conv output tf32-rounded
__device__ __align__(16) float g_norm[(long)BB * LL * DD];         // l2norm(conv), rounded
__device__ __align__(16) float g_scores[(long)BB * LL * LL];       // attention (rounded post-softmax)
__device__ __align__(16) float g_result[(long)BB * LL * NH * DD];  // [B,L,4,D] fp32
__device__ __align__(16) float g_resultr[(long)BB * LL * NH * DD]; // rounded copy (pool GEMM A)
__device__ __align__(16) float g_hidden[(long)BB * LL * NH * DD];  // tanh(result@W1+b1)
__device__ __align__(16) float g_wt[(long)HOPS * 3 * DD * DD];     // conv weights K-major rounded
__device__ __align__(16) float g_inr[(long)BB * LL * DD];          // inputs tf32-rounded
__device__ __align__(16) float g_w1r[(long)DD * DD];               // pool_w1 rounded

// ---- fp32 -> tf32 round-to-nearest (bias-free) ----
__device__ __forceinline__ float f2tf32(float x) {
    unsigned y;
    asm("cvt.rna.tf32.f32 %0, %1;" : "=r"(y) : "f"(x));
    return __uint_as_float(y);
}

__device__ __forceinline__ void mma_tf32(float c[4],
                                         unsigned a0, unsigned a1, unsigned a2, unsigned a3,
                                         unsigned b0, unsigned b1) {
    asm volatile(
        "mma.sync.aligned.m16n8k8.row.col.f32.tf32.tf32.f32 "
        "{%0,%1,%2,%3}, {%4,%5,%6,%7}, {%8,%9}, {%0,%1,%2,%3};"
        : "+f"(c[0]), "+f"(c[1]), "+f"(c[2]), "+f"(c[3])
        : "r"(a0), "r"(a1), "r"(a2), "r"(a3), "r"(b0), "r"(b1));
}

__device__ __forceinline__ void cp16(void* smem_dst, const void* gsrc) {
    unsigned d = (unsigned)__cvta_generic_to_shared(smem_dst);
    asm volatile("cp.async.cg.shared.global [%0], [%1], 16;" :: "r"(d), "l"(gsrc));
}
__device__ __forceinline__ void cp_commit() {
    asm volatile("cp.async.commit_group;");
}
template <int N>
__device__ __forceinline__ void cp_wait() {
    asm volatile("cp.async.wait_group %0;" :: "n"(N));
}

// ---------------- tensor-core 128x128x16 GEMM, 3-stage cp.async pipeline ----
// Operands MUST be pre-rounded to tf32. C[M,N] = A[M,K] * B (+ epilogue).
// BT=true : B is [N,K] row-major (NT). BT=false: B is [K,N] row-major (NN).
// EPI: 0 none, 1 relu(x+bias[n]), 2 tanh(x+bias[n])
// WR: also write tf32-rounded copy of C into Caux (same geometry).
template <bool BT, int EPI, bool WR>
__global__ __launch_bounds__(256, 2) void gemm_tc(
    const float* __restrict__ A, const float* __restrict__ Bm,
    float* __restrict__ C, float* __restrict__ Caux, const float* __restrict__ bias,
    int K, int lda, int ldb, int ldc,
    long sA, long sB, long sC)
{
    constexpr int BM = 128, BN = 128, BK = 16, S = 3;
    constexpr int BKP = 20;   // 16 + 4 pad (80B rows, 16B aligned, LDS conflict-free)
    constexpr int BNP = 136;  // 128 + 8 pad (544B rows, 16B aligned, LDS conflict-free)

    extern __shared__ float sm[];
    float* Asm = sm;                          // [S][BM][BKP]
    float* Bsm = sm + (long)S * BM * BKP;     // NT: [S][BN][BKP] ; NN: [S][BK][BNP]

    const int tid = threadIdx.x;
    const int bx = blockIdx.x, by = blockIdx.y, bz = blockIdx.z;

    const float* Ab = A + (long)bz * sA + (long)by * BM * lda;
    const float* Bb;
    if (BT) Bb = Bm + (long)bz * sB + (long)bx * BN * ldb;
    else    Bb = Bm + (long)bz * sB + bx * BN;

    const int wid  = tid >> 5;
    const int lane = tid & 31;
    const int wm = (wid & 1) * 64;   // 2 warps in M
    const int wn = (wid >> 1) * 32;  // 4 warps in N
    const int gid = lane >> 2;       // 0..7
    const int tig = lane & 3;        // 0..3

    float acc[4][4][4];
#pragma unroll
    for (int mt = 0; mt < 4; mt++)
#pragma unroll
        for (int nt = 0; nt < 4; nt++)
#pragma unroll
            for (int r = 0; r < 4; r++) acc[mt][nt][r] = 0.f;

    const int KT = K / BK;

    auto issue_copy = [&](int kt, int s) {
        const int k0 = kt * BK;
        float* As = Asm + (long)s * BM * BKP;
#pragma unroll
        for (int t = 0; t < 2; t++) {
            int id  = tid + t * 256;
            int row = id >> 2;
            int c4  = (id & 3) * 4;
            cp16(As + (long)row * BKP + c4, Ab + (long)row * lda + k0 + c4);
        }
        if (BT) {
            float* Bs = Bsm + (long)s * BN * BKP;
#pragma unroll
            for (int t = 0; t < 2; t++) {
                int id  = tid + t * 256;
                int row = id >> 2;
                int c4  = (id & 3) * 4;
                cp16(Bs + (long)row * BKP + c4, Bb + (long)row * ldb + k0 + c4);
            }
        } else {
            float* Bs = Bsm + (long)s * BK * BNP;
#pragma unroll
            for (int t = 0; t < 2; t++) {
                int id  = tid + t * 256;
                int row = id >> 5;        // k 0..15
                int c4  = (id & 31) * 4;  // n
                cp16(Bs + (long)row * BNP + c4, Bb + (long)(k0 + row) * ldb + c4);
            }
        }
        cp_commit();
    };

    // prologue: stages 0..S-2
#pragma unroll
    for (int s = 0; s < S - 1; s++) issue_copy(s, s);

    for (int kt = 0; kt < KT; kt++) {
        const int s = kt % S;
        cp_wait<S - 2>();      // tile kt resident
        __syncthreads();       // all warps done with compute(kt-1)

        const int pre = kt + S - 1;
        if (pre < KT) issue_copy(pre, pre % S);

        const float* As = Asm + (long)s * BM * BKP;
        const float* BsNT = Bsm + (long)s * BN * BKP;
        const float* BsNN = Bsm + (long)s * BK * BNP;

#pragma unroll
        for (int ks = 0; ks < BK; ks += 8) {
            unsigned bf[4][2];
#pragma unroll
            for (int nt = 0; nt < 4; nt++) {
                const int n = wn + nt * 8 + gid;
                if (BT) {
                    bf[nt][0] = __float_as_uint(BsNT[(long)n * BKP + ks + tig]);
                    bf[nt][1] = __float_as_uint(BsNT[(long)n * BKP + ks + tig + 4]);
                } else {
                    bf[nt][0] = __float_as_uint(BsNN[(long)(ks + tig) * BNP + n]);
                    bf[nt][1] = __float_as_uint(BsNN[(long)(ks + tig + 4) * BNP + n]);
                }
            }
#pragma unroll
            for (int mt = 0; mt < 4; mt++) {
                const int m = wm + mt * 16 + gid;
                unsigned a0 = __float_as_uint(As[(long)m * BKP + ks + tig]);
                unsigned a1 = __float_as_uint(As[(long)(m + 8) * BKP + ks + tig]);
                unsigned a2 = __float_as_uint(As[(long)m * BKP + ks + tig + 4]);
                unsigned a3 = __float_as_uint(As[(long)(m + 8) * BKP + ks + tig + 4]);
#pragma unroll
                for (int nt = 0; nt < 4; nt++)
                    mma_tf32(acc[mt][nt], a0, a1, a2, a3, bf[nt][0], bf[nt][1]);
            }
        }
    }

    float* Cb = C + (long)bz * sC + (long)(by * BM) * ldc + bx * BN;
    float* Xb = Caux + (long)bz * sC + (long)(by * BM) * ldc + bx * BN;
#pragma unroll
    for (int nt = 0; nt < 4; nt++) {
        const int c = wn + nt * 8 + 2 * tig;
        float b0 = 0.f, b1 = 0.f;
        if (EPI != 0) {
            b0 = bias[bx * BN + c];
            b1 = bias[bx * BN + c + 1];
        }
#pragma unroll
        for (int mt = 0; mt < 4; mt++) {
            const int r0 = wm + mt * 16 + gid;
            float v0 = acc[mt][nt][0], v1 = acc[mt][nt][1];
            float v2 = acc[mt][nt][2], v3 = acc[mt][nt][3];
            if (EPI == 1) {
                v0 = fmaxf(v0 + b0, 0.f); v1 = fmaxf(v1 + b1, 0.f);
                v2 = fmaxf(v2 + b0, 0.f); v3 = fmaxf(v3 + b1, 0.f);
            } else if (EPI == 2) {
                v0 = tanhf(v0 + b0); v1 = tanhf(v1 + b1);
                v2 = tanhf(v2 + b0); v3 = tanhf(v3 + b1);
            }
            *reinterpret_cast<float2*>(Cb + (long)r0 * ldc + c)       = make_float2(v0, v1);
            *reinterpret_cast<float2*>(Cb + (long)(r0 + 8) * ldc + c) = make_float2(v2, v3);
            if (WR) {
                *reinterpret_cast<float2*>(Xb + (long)r0 * ldc + c) =
                    make_float2(f2tf32(v0), f2tf32(v1));
                *reinterpret_cast<float2*>(Xb + (long)(r0 + 8) * ldc + c) =
                    make_float2(f2tf32(v2), f2tf32(v3));
            }
        }
    }
}

// ---------------- tf32-round a buffer (float4 granularity) ------------------
__global__ void round_kernel(const float* __restrict__ src, float* __restrict__ dst, int n)
{
    for (int i = blockIdx.x * blockDim.x + threadIdx.x; i * 4 < n;
         i += gridDim.x * blockDim.x) {
        float4 v = *reinterpret_cast<const float4*>(src + i * 4);
        v.x = f2tf32(v.x); v.y = f2tf32(v.y); v.z = f2tf32(v.z); v.w = f2tf32(v.w);
        *reinterpret_cast<float4*>(dst + i * 4) = v;
    }
}

// ---------------- masked softmax over rows of [B,L,L]; rounded output -------
__global__ void softmask_kernel(float* __restrict__ S, const float* __restrict__ mask)
{
    int gw   = (blockIdx.x * blockDim.x + threadIdx.x) >> 5;
    int lane = threadIdx.x & 31;
    if (gw >= BB * LL) return;
    int b = gw / LL;
    int l = gw - b * LL;
    float* row = S + (long)gw * LL;
    const float* mk = mask + (long)b * LL;

    float v[16];
    float mx = -1e30f;
#pragma unroll
    for (int t = 0; t < 16; t++) {
        v[t] = row[lane + t * 32];
        mx = fmaxf(mx, v[t]);
    }
#pragma unroll
    for (int o = 16; o; o >>= 1) mx = fmaxf(mx, __shfl_xor_sync(0xffffffffu, mx, o));

    float sum = 0.f;
#pragma unroll
    for (int t = 0; t < 16; t++) {
        float e = __expf(v[t] - mx) * mk[lane + t * 32];
        v[t] = e;
        sum += e;
    }
#pragma unroll
    for (int o = 16; o; o >>= 1) sum += __shfl_xor_sync(0xffffffffu, sum, o);

    float scale = mk[l] / (sum + 1e-10f);
#pragma unroll
    for (int t = 0; t < 16; t++) row[lane + t * 32] = f2tf32(v[t] * scale);
}

// ---------------- L2 normalize rows of [B*L, D]; rounded output -------------
__global__ void l2norm_kernel(const float* __restrict__ X, float* __restrict__ Y)
{
    int gw   = (blockIdx.x * blockDim.x + threadIdx.x) >> 5;
    int lane = threadIdx.x & 31;
    if (gw >= BB * LL) return;
    const float* x = X + (long)gw * DD;
    float* y = Y + (long)gw * DD;
    float ss = 0.f;
#pragma unroll
    for (int t = 0; t < 24; t++) {
        float v = x[lane + t * 32];
        ss += v * v;
    }
#pragma unroll
    for (int o = 16; o; o >>= 1) ss += __shfl_xor_sync(0xffffffffu, ss, o);
    float scale = 1.f / fmaxf(sqrtf(ss), 1e-12f);
#pragma unroll
    for (int t = 0; t < 24; t++) y[lane + t * 32] = f2tf32(x[lane + t * 32] * scale);
}

// ---------------- zero-padded cur for conv; rounded output ------------------
__global__ void pad_kernel(const float* __restrict__ X)
{
    const int n = BB * (LL + 2) * DD;
    for (int i = blockIdx.x * blockDim.x + threadIdx.x; i < n;
         i += gridDim.x * blockDim.x) {
        int bi = i / ((LL + 2) * DD);
        int r  = (i / DD) % (LL + 2);
        int d  = i % DD;
        float v = 0.f;
        if (r >= 1 && r <= LL) v = f2tf32(X[((long)bi * LL + (r - 1)) * DD + d]);
        g_xpad[i] = v;
    }
}

// ------- conv weight transpose: W[h][o][i][k] -> Wt[h][k*D+i][o]; rounded ----
__global__ void wtrans_kernel(const float* __restrict__ W)
{
    const long n = (long)HOPS * 3 * DD * DD;
    for (long i = blockIdx.x * (long)blockDim.x + threadIdx.x; i < n;
         i += (long)gridDim.x * blockDim.x) {
        long h    = i / (3L * DD * DD);
        long rem  = i - h * 3L * DD * DD;
        long k    = rem / ((long)DD * DD);
        long rem2 = rem - k * (long)DD * DD;
        long ii   = rem2 / DD;
        long o    = rem2 - ii * DD;
        g_wt[i] = f2tf32(W[((h * DD + o) * DD + ii) * 3 + k]);
    }
}

// ---------------- pooling tail ----------------------------------------------
__global__ void pool_finalize_kernel(const float* __restrict__ w2,
                                     const float* __restrict__ b2,
                                     float* __restrict__ out)
{
    int gw   = (blockIdx.x * blockDim.x + threadIdx.x) >> 5;
    int lane = threadIdx.x & 31;
    if (gw >= BB * LL) return;
    const float* hid = g_hidden + (long)gw * NH * DD;
    const float* res = g_result + (long)gw * NH * DD;

    float s[NH];
#pragma unroll
    for (int h = 0; h < NH; h++) {
        float dot = 0.f;
#pragma unroll
        for (int t = 0; t < 24; t++) {
            int d = lane + t * 32;
            dot += hid[h * DD + d] * w2[d];
        }
#pragma unroll
        for (int o = 16; o; o >>= 1) dot += __shfl_xor_sync(0xffffffffu, dot, o);
        s[h] = dot + b2[0];
    }
    float mx = fmaxf(fmaxf(s[0], s[1]), fmaxf(s[2], s[3]));
    float e0 = __expf(s[0] - mx), e1 = __expf(s[1] - mx);
    float e2 = __expf(s[2] - mx), e3 = __expf(s[3] - mx);
    float inv = 1.f / (e0 + e1 + e2 + e3);
    e0 *= inv; e1 *= inv; e2 *= inv; e3 *= inv;

    float* o = out + (long)gw * DD;
#pragma unroll
    for (int t = 0; t < 24; t++) {
        int d = lane + t * 32;
        o[d] = e0 * res[d] + e1 * res[DD + d] + e2 * res[2 * DD + d] + e3 * res[3 * DD + d];
    }
}

__global__ void copy_kernel(const float* __restrict__ src, float* __restrict__ dst, int n)
{
    for (int i = blockIdx.x * blockDim.x + threadIdx.x; i * 4 < n;
         i += gridDim.x * blockDim.x) {
        *reinterpret_cast<float4*>(dst + i * 4) =
            *reinterpret_cast<const float4*>(src + i * 4);
    }
}

// ---------------- orchestration ---------------------------------------------
extern "C" void kernel_launch(void* const* d_in, const int* in_sizes, int n_in,
                              void* d_out, int out_size)
{
    (void)in_sizes; (void)n_in; (void)out_size;
    const float* inputs  = (const float*)d_in[0];
    const float* mask    = (const float*)d_in[1];
    const float* conv_w  = (const float*)d_in[2];
    const float* conv_b  = (const float*)d_in[3];
    const float* pool_w1 = (const float*)d_in[4];
    const float* pool_b1 = (const float*)d_in[5];
    const float* pool_w2 = (const float*)d_in[6];
    const float* pool_b2 = (const float*)d_in[7];
    float* out = (float*)d_out;

    float *xpad, *conv, *convr, *nrm, *scores, *result, *resultr, *hidden, *wt, *inr, *w1r;
    cudaGetSymbolAddress((void**)&xpad,    g_xpad);
    cudaGetSymbolAddress((void**)&conv,    g_conv);
    cudaGetSymbolAddress((void**)&convr,   g_convr);
    cudaGetSymbolAddress((void**)&nrm,     g_norm);
    cudaGetSymbolAddress((void**)&scores,  g_scores);
    cudaGetSymbolAddress((void**)&result,  g_result);
    cudaGetSymbolAddress((void**)&resultr, g_resultr);
    cudaGetSymbolAddress((void**)&hidden,  g_hidden);
    cudaGetSymbolAddress((void**)&wt,      g_wt);
    cudaGetSymbolAddress((void**)&inr,     g_inr);
    cudaGetSymbolAddress((void**)&w1r,     g_w1r);

    // dynamic smem opt-in (host-side attribute set; not a stream op)
    constexpr int SM_NT = 3 * (128 * 20 + 128 * 20) * 4;  // 61440
    constexpr int SM_NN = 3 * (128 * 20 + 16 * 136) * 4;  // 56832
    cudaFuncSetAttribute(gemm_tc<true, 0, false>,
                         cudaFuncAttributeMaxDynamicSharedMemorySize, SM_NT);
    cudaFuncSetAttribute(gemm_tc<false, 0, true>,
                         cudaFuncAttributeMaxDynamicSharedMemorySize, SM_NN);
    cudaFuncSetAttribute(gemm_tc<false, 1, true>,
                         cudaFuncAttributeMaxDynamicSharedMemorySize, SM_NN);
    cudaFuncSetAttribute(gemm_tc<false, 2, false>,
                         cudaFuncAttributeMaxDynamicSharedMemorySize, SM_NN);

    // pre-round constant operands
    round_kernel<<<1024, 256>>>(inputs, inr, BB * LL * DD);
    round_kernel<<<128, 256>>>(pool_w1, w1r, DD * DD);
    wtrans_kernel<<<256, 256>>>(conv_w);

    // ---- hop 0: raw similarity on inputs ----
    gemm_tc<true, 0, false><<<dim3(LL / 128, LL / 128, BB), 256, SM_NT>>>(
        inr, inr, scores, nullptr, nullptr,
        DD, DD, DD, LL, (long)LL * DD, (long)LL * DD, (long)LL * LL);
    softmask_kernel<<<BB * LL / 8, 256>>>(scores, mask);
    gemm_tc<false, 0, true><<<dim3(DD / 128, LL / 128, BB), 256, SM_NN>>>(
        scores, inr, result, resultr, nullptr,
        LL, LL, DD, NH * DD, (long)LL * LL, (long)LL * DD, (long)LL * NH * DD);

    // ---- hops 1..3 ----
    const float* cur = inputs;
    for (int h = 0; h < HOPS; h++) {
        pad_kernel<<<1024, 256>>>(cur);
        gemm_tc<false, 1, true><<<dim3(DD / 128, LL / 128, BB), 256, SM_NN>>>(
            xpad, wt + (long)h * 3 * DD * DD, conv, convr, conv_b + h * DD,
            3 * DD, DD, DD, DD, (long)(LL + 2) * DD, 0L, (long)LL * DD);
        l2norm_kernel<<<BB * LL / 8, 256>>>(conv, nrm);
        gemm_tc<true, 0, false><<<dim3(LL / 128, LL / 128, BB), 256, SM_NT>>>(
            nrm, nrm, scores, nullptr, nullptr,
            DD, DD, DD, LL, (long)LL * DD, (long)LL * DD, (long)LL * LL);
        softmask_kernel<<<BB * LL / 8, 256>>>(scores, mask);
        gemm_tc<false, 0, true><<<dim3(DD / 128, LL / 128, BB), 256, SM_NN>>>(
            scores, convr, result + (long)(h + 1) * DD, resultr + (long)(h + 1) * DD, nullptr,
            LL, LL, DD, NH * DD, (long)LL * LL, (long)LL * DD, (long)LL * NH * DD);
        cur = conv;
    }

    // output #1: cur (fp32)
    copy_kernel<<<1024, 256>>>(conv, out, BB * LL * DD);

    // pooling: hidden = tanh(result @ W1 + b1)
    gemm_tc<false, 2, false><<<dim3(DD / 128, (BB * LL * NH) / 128, 1), 256, SM_NN>>>(
        resultr, w1r, hidden, nullptr, pool_b1,
        DD, DD, DD, DD, 0L, 0L, 0L);

    // output #2: weighted
    pool_finalize_kernel<<<BB * LL / 8, 256>>>(pool_w2, pool_b2, out + (long)BB * LL * DD);
}

// round 5
// speedup vs baseline: 3.2364x; 1.1388x over previous
#include <cuda_runtime.h>
#include <math.h>

#define BB 16
#define LL 512
#define DD 768
#define HOPS 3
#define NH (HOPS + 1)

// ---------------- scratch (static device globals; no allocs) ----------------
__device__ __align__(16) float g_conv[(long)BB * LL * DD];          // conv output fp32 (hops 1-2)
__device__ __align__(16) float g_convr0[(long)BB * LL * DD];        // rounded conv (ping)
__device__ __align__(16) float g_convr1[(long)BB * LL * DD];        // rounded conv (pong)
__device__ __align__(16) float g_norm[(long)BB * LL * DD];          // l2norm(conv), rounded
__device__ __align__(16) float g_scores[(long)BB * LL * LL];        // attention (rounded post-softmax)
__device__ __align__(16) float g_result[(long)BB * LL * NH * DD];   // [B,L,4,D] fp32
__device__ __align__(16) float g_resultr[(long)BB * LL * NH * DD];  // rounded copy (pool GEMM A)
__device__ __align__(16) float g_hidden[(long)BB * LL * NH * DD];   // tanh(result@W1+b1)
__device__ __align__(16) float g_wt[(long)HOPS * 3 * DD * DD];      // conv weights K-major rounded
__device__ __align__(16) float g_inr[(long)BB * LL * DD];           // inputs tf32-rounded
__device__ __align__(16) float g_w1r[(long)DD * DD];                // pool_w1 rounded

// ---- fp32 -> tf32 round-to-nearest (bias-free) ----
__device__ __forceinline__ float f2tf32(float x) {
    unsigned y;
    asm("cvt.rna.tf32.f32 %0, %1;" : "=r"(y) : "f"(x));
    return __uint_as_float(y);
}

__device__ __forceinline__ void mma_tf32(float c[4],
                                         unsigned a0, unsigned a1, unsigned a2, unsigned a3,
                                         unsigned b0, unsigned b1) {
    asm volatile(
        "mma.sync.aligned.m16n8k8.row.col.f32.tf32.tf32.f32 "
        "{%0,%1,%2,%3}, {%4,%5,%6,%7}, {%8,%9}, {%0,%1,%2,%3};"
        : "+f"(c[0]), "+f"(c[1]), "+f"(c[2]), "+f"(c[3])
        : "r"(a0), "r"(a1), "r"(a2), "r"(a3), "r"(b0), "r"(b1));
}

__device__ __forceinline__ void cp16(void* smem_dst, const void* gsrc) {
    unsigned d = (unsigned)__cvta_generic_to_shared(smem_dst);
    asm volatile("cp.async.cg.shared.global [%0], [%1], 16;" :: "r"(d), "l"(gsrc));
}
// predicated: pred=false -> zero-fill 16B (src not read)
__device__ __forceinline__ void cp16z(void* smem_dst, const void* gsrc, bool ok) {
    unsigned d = (unsigned)__cvta_generic_to_shared(smem_dst);
    int sz = ok ? 16 : 0;
    asm volatile("cp.async.cg.shared.global [%0], [%1], 16, %2;" :: "r"(d), "l"(gsrc), "r"(sz));
}
__device__ __forceinline__ void cp_commit() {
    asm volatile("cp.async.commit_group;");
}
template <int N>
__device__ __forceinline__ void cp_wait() {
    asm volatile("cp.async.wait_group %0;" :: "n"(N));
}

// ---------------- tensor-core 128x128x32 GEMM, 3-stage cp.async pipeline ----
// Operands pre-rounded to tf32. C[M,N] = A[M,K] * B (+ epilogue).
// MODE 0: NT — B is [N,K] row-major.
// MODE 1: NN — B is [K,N] row-major.
// MODE 2: NN-conv — like MODE 1, but A is implicit im2col of a [L,D] sequence
//         (token = row - 1 + k/768, zero-padded at sequence ends), K = 3*768.
// EPI: 0 none, 1 relu(x+bias[n]), 2 tanh(x+bias[n])
// WR: also write tf32-rounded copy of C into Caux (must NOT alias A/B).
template <int MODE, int EPI, bool WR>
__global__ __launch_bounds__(256, 2) void gemm_tc(
    const float* __restrict__ A, const float* __restrict__ Bm,
    float* __restrict__ C, float* __restrict__ Caux, const float* __restrict__ bias,
    int K, int lda, int ldb, int ldc,
    long sA, long sB, long sC)
{
    constexpr int BM = 128, BN = 128, BK = 32, S = 3;
    constexpr int BKP = 36;   // 32 + 4 pad (144B rows; 16B aligned; LDS conflict-free)
    constexpr int BNP = 136;  // 128 + 8 pad (544B rows)
    constexpr bool BT = (MODE == 0);

    extern __shared__ float sm[];
    float* Asm = sm;                          // [S][BM][BKP]
    float* Bsm = sm + (long)S * BM * BKP;     // NT: [S][BN][BKP] ; NN: [S][BK][BNP]

    const int tid = threadIdx.x;
    const int bx = blockIdx.x, by = blockIdx.y, bz = blockIdx.z;

    const float* Ab = A + (long)bz * sA + (MODE == 2 ? 0L : (long)by * BM * lda);
    const float* Bb;
    if (BT) Bb = Bm + (long)bz * sB + (long)bx * BN * ldb;
    else    Bb = Bm + (long)bz * sB + bx * BN;

    const int wid  = tid >> 5;
    const int lane = tid & 31;
    const int wm = (wid & 1) * 64;   // 2 warps in M
    const int wn = (wid >> 1) * 32;  // 4 warps in N
    const int gid = lane >> 2;       // 0..7
    const int tig = lane & 3;        // 0..3

    float acc[4][4][4];
#pragma unroll
    for (int mt = 0; mt < 4; mt++)
#pragma unroll
        for (int nt = 0; nt < 4; nt++)
#pragma unroll
            for (int r = 0; r < 4; r++) acc[mt][nt][r] = 0.f;

    const int KT = K / BK;

    auto issue_copy = [&](int kt, int s) {
        const int k0 = kt * BK;
        float* As = Asm + (long)s * BM * BKP;
        // A tile: 128 rows x 32 floats = 1024 16B-chunks, 4 per thread
#pragma unroll
        for (int t = 0; t < 4; t++) {
            int id  = tid + t * 256;
            int row = id >> 3;          // 0..127
            int c4  = (id & 7) * 4;     // 0,4,...,28
            if (MODE == 2) {
                int k   = k0 + c4;                       // 0..2300
                int sub = (k >= 1536) ? 2 : (k >= 768 ? 1 : 0);
                int tok = by * BM + row - 1 + sub;
                int d   = k - sub * 768;
                bool ok = ((unsigned)tok < (unsigned)LL);
                int tc  = ok ? tok : 0;
                cp16z(As + (long)row * BKP + c4, Ab + (long)tc * DD + d, ok);
            } else {
                cp16(As + (long)row * BKP + c4, Ab + (long)row * lda + k0 + c4);
            }
        }
        if (BT) {
            float* Bs = Bsm + (long)s * BN * BKP;
#pragma unroll
            for (int t = 0; t < 4; t++) {
                int id  = tid + t * 256;
                int row = id >> 3;
                int c4  = (id & 7) * 4;
                cp16(Bs + (long)row * BKP + c4, Bb + (long)row * ldb + k0 + c4);
            }
        } else {
            float* Bs = Bsm + (long)s * BK * BNP;
#pragma unroll
            for (int t = 0; t < 4; t++) {
                int id  = tid + t * 256;
                int row = id >> 5;          // k 0..31
                int c4  = (id & 31) * 4;    // n
                cp16(Bs + (long)row * BNP + c4, Bb + (long)(k0 + row) * ldb + c4);
            }
        }
        cp_commit();
    };

    // prologue: stages 0..S-2
#pragma unroll
    for (int s = 0; s < S - 1; s++) issue_copy(s, s);

    for (int kt = 0; kt < KT; kt++) {
        const int s = kt % S;
        cp_wait<S - 2>();      // tile kt resident
        __syncthreads();       // all warps done with compute(kt-1) -> stage (kt+S-1)%S reusable

        const int pre = kt + S - 1;
        if (pre < KT) issue_copy(pre, pre % S);

        const float* As = Asm + (long)s * BM * BKP;
        const float* BsNT = Bsm + (long)s * BN * BKP;
        const float* BsNN = Bsm + (long)s * BK * BNP;

#pragma unroll
        for (int ks = 0; ks < BK; ks += 8) {
            unsigned bf[4][2];
#pragma unroll
            for (int nt = 0; nt < 4; nt++) {
                const int n = wn + nt * 8 + gid;
                if (BT) {
                    bf[nt][0] = __float_as_uint(BsNT[(long)n * BKP + ks + tig]);
                    bf[nt][1] = __float_as_uint(BsNT[(long)n * BKP + ks + tig + 4]);
                } else {
                    bf[nt][0] = __float_as_uint(BsNN[(long)(ks + tig) * BNP + n]);
                    bf[nt][1] = __float_as_uint(BsNN[(long)(ks + tig + 4) * BNP + n]);
                }
            }
#pragma unroll
            for (int mt = 0; mt < 4; mt++) {
                const int m = wm + mt * 16 + gid;
                unsigned a0 = __float_as_uint(As[(long)m * BKP + ks + tig]);
                unsigned a1 = __float_as_uint(As[(long)(m + 8) * BKP + ks + tig]);
                unsigned a2 = __float_as_uint(As[(long)m * BKP + ks + tig + 4]);
                unsigned a3 = __float_as_uint(As[(long)(m + 8) * BKP + ks + tig + 4]);
#pragma unroll
                for (int nt = 0; nt < 4; nt++)
                    mma_tf32(acc[mt][nt], a0, a1, a2, a3, bf[nt][0], bf[nt][1]);
            }
        }
    }

    float* Cb = C + (long)bz * sC + (long)(by * BM) * ldc + bx * BN;
    float* Xb = Caux + (long)bz * sC + (long)(by * BM) * ldc + bx * BN;
#pragma unroll
    for (int nt = 0; nt < 4; nt++) {
        const int c = wn + nt * 8 + 2 * tig;
        float b0 = 0.f, b1 = 0.f;
        if (EPI != 0) {
            b0 = bias[bx * BN + c];
            b1 = bias[bx * BN + c + 1];
        }
#pragma unroll
        for (int mt = 0; mt < 4; mt++) {
            const int r0 = wm + mt * 16 + gid;
            float v0 = acc[mt][nt][0], v1 = acc[mt][nt][1];
            float v2 = acc[mt][nt][2], v3 = acc[mt][nt][3];
            if (EPI == 1) {
                v0 = fmaxf(v0 + b0, 0.f); v1 = fmaxf(v1 + b1, 0.f);
                v2 = fmaxf(v2 + b0, 0.f); v3 = fmaxf(v3 + b1, 0.f);
            } else if (EPI == 2) {
                v0 = tanhf(v0 + b0); v1 = tanhf(v1 + b1);
                v2 = tanhf(v2 + b0); v3 = tanhf(v3 + b1);
            }
            *reinterpret_cast<float2*>(Cb + (long)r0 * ldc + c)       = make_float2(v0, v1);
            *reinterpret_cast<float2*>(Cb + (long)(r0 + 8) * ldc + c) = make_float2(v2, v3);
            if (WR) {
                *reinterpret_cast<float2*>(Xb + (long)r0 * ldc + c) =
                    make_float2(f2tf32(v0), f2tf32(v1));
                *reinterpret_cast<float2*>(Xb + (long)(r0 + 8) * ldc + c) =
                    make_float2(f2tf32(v2), f2tf32(v3));
            }
        }
    }
}

// ---------------- tf32-round a buffer (float4 granularity) ------------------
__global__ void round_kernel(const float* __restrict__ src, float* __restrict__ dst, int n)
{
    for (int i = blockIdx.x * blockDim.x + threadIdx.x; i * 4 < n;
         i += gridDim.x * blockDim.x) {
        float4 v = *reinterpret_cast<const float4*>(src + i * 4);
        v.x = f2tf32(v.x); v.y = f2tf32(v.y); v.z = f2tf32(v.z); v.w = f2tf32(v.w);
        *reinterpret_cast<float4*>(dst + i * 4) = v;
    }
}

// ---------------- masked softmax over rows of [B,L,L]; rounded output -------
__global__ void softmask_kernel(float* __restrict__ S, const float* __restrict__ mask)
{
    int gw   = (blockIdx.x * blockDim.x + threadIdx.x) >> 5;
    int lane = threadIdx.x & 31;
    if (gw >= BB * LL) return;
    int b = gw / LL;
    int l = gw - b * LL;
    float* row = S + (long)gw * LL;
    const float* mk = mask + (long)b * LL;

    float v[16];
    float mx = -1e30f;
#pragma unroll
    for (int t = 0; t < 16; t++) {
        v[t] = row[lane + t * 32];
        mx = fmaxf(mx, v[t]);
    }
#pragma unroll
    for (int o = 16; o; o >>= 1) mx = fmaxf(mx, __shfl_xor_sync(0xffffffffu, mx, o));

    float sum = 0.f;
#pragma unroll
    for (int t = 0; t < 16; t++) {
        float e = __expf(v[t] - mx) * mk[lane + t * 32];
        v[t] = e;
        sum += e;
    }
#pragma unroll
    for (int o = 16; o; o >>= 1) sum += __shfl_xor_sync(0xffffffffu, sum, o);

    float scale = mk[l] / (sum + 1e-10f);
#pragma unroll
    for (int t = 0; t < 16; t++) row[lane + t * 32] = f2tf32(v[t] * scale);
}

// ---------------- L2 normalize rows of [B*L, D]; rounded output -------------
__global__ void l2norm_kernel(const float* __restrict__ X, float* __restrict__ Y)
{
    int gw   = (blockIdx.x * blockDim.x + threadIdx.x) >> 5;
    int lane = threadIdx.x & 31;
    if (gw >= BB * LL) return;
    const float* x = X + (long)gw * DD;
    float* y = Y + (long)gw * DD;
    float ss = 0.f;
#pragma unroll
    for (int t = 0; t < 24; t++) {
        float v = x[lane + t * 32];
        ss += v * v;
    }
#pragma unroll
    for (int o = 16; o; o >>= 1) ss += __shfl_xor_sync(0xffffffffu, ss, o);
    float scale = 1.f / fmaxf(sqrtf(ss), 1e-12f);
#pragma unroll
    for (int t = 0; t < 24; t++) y[lane + t * 32] = f2tf32(x[lane + t * 32] * scale);
}

// ------- conv weight transpose: W[h][o][i][k] -> Wt[h][k*D+i][o]; rounded ----
__global__ void wtrans_kernel(const float* __restrict__ W)
{
    const long n = (long)HOPS * 3 * DD * DD;
    for (long i = blockIdx.x * (long)blockDim.x + threadIdx.x; i < n;
         i += (long)gridDim.x * blockDim.x) {
        long h    = i / (3L * DD * DD);
        long rem  = i - h * 3L * DD * DD;
        long k    = rem / ((long)DD * DD);
        long rem2 = rem - k * (long)DD * DD;
        long ii   = rem2 / DD;
        long o    = rem2 - ii * DD;
        g_wt[i] = f2tf32(W[((h * DD + o) * DD + ii) * 3 + k]);
    }
}

// ---------------- pooling tail ----------------------------------------------
__global__ void pool_finalize_kernel(const float* __restrict__ w2,
                                     const float* __restrict__ b2,
                                     float* __restrict__ out)
{
    int gw   = (blockIdx.x * blockDim.x + threadIdx.x) >> 5;
    int lane = threadIdx.x & 31;
    if (gw >= BB * LL) return;
    const float* hid = g_hidden + (long)gw * NH * DD;
    const float* res = g_result + (long)gw * NH * DD;

    float s[NH];
#pragma unroll
    for (int h = 0; h < NH; h++) {
        float dot = 0.f;
#pragma unroll
        for (int t = 0; t < 24; t++) {
            int d = lane + t * 32;
            dot += hid[h * DD + d] * w2[d];
        }
#pragma unroll
        for (int o = 16; o; o >>= 1) dot += __shfl_xor_sync(0xffffffffu, dot, o);
        s[h] = dot + b2[0];
    }
    float mx = fmaxf(fmaxf(s[0], s[1]), fmaxf(s[2], s[3]));
    float e0 = __expf(s[0] - mx), e1 = __expf(s[1] - mx);
    float e2 = __expf(s[2] - mx), e3 = __expf(s[3] - mx);
    float inv = 1.f / (e0 + e1 + e2 + e3);
    e0 *= inv; e1 *= inv; e2 *= inv; e3 *= inv;

    float* o = out + (long)gw * DD;
#pragma unroll
    for (int t = 0; t < 24; t++) {
        int d = lane + t * 32;
        o[d] = e0 * res[d] + e1 * res[DD + d] + e2 * res[2 * DD + d] + e3 * res[3 * DD + d];
    }
}

// ---------------- orchestration ---------------------------------------------
extern "C" void kernel_launch(void* const* d_in, const int* in_sizes, int n_in,
                              void* d_out, int out_size)
{
    (void)in_sizes; (void)n_in; (void)out_size;
    const float* inputs  = (const float*)d_in[0];
    const float* mask    = (const float*)d_in[1];
    const float* conv_w  = (const float*)d_in[2];
    const float* conv_b  = (const float*)d_in[3];
    const float* pool_w1 = (const float*)d_in[4];
    const float* pool_b1 = (const float*)d_in[5];
    const float* pool_w2 = (const float*)d_in[6];
    const float* pool_b2 = (const float*)d_in[7];
    float* out = (float*)d_out;

    float *conv, *convr0, *convr1, *nrm, *scores, *result, *resultr, *hidden, *wt, *inr, *w1r;
    cudaGetSymbolAddress((void**)&conv,    g_conv);
    cudaGetSymbolAddress((void**)&convr0,  g_convr0);
    cudaGetSymbolAddress((void**)&convr1,  g_convr1);
    cudaGetSymbolAddress((void**)&nrm,     g_norm);
    cudaGetSymbolAddress((void**)&scores,  g_scores);
    cudaGetSymbolAddress((void**)&result,  g_result);
    cudaGetSymbolAddress((void**)&resultr, g_resultr);
    cudaGetSymbolAddress((void**)&hidden,  g_hidden);
    cudaGetSymbolAddress((void**)&wt,      g_wt);
    cudaGetSymbolAddress((void**)&inr,     g_inr);
    cudaGetSymbolAddress((void**)&w1r,     g_w1r);

    constexpr int S = 3;
    constexpr int SM_NT = S * (128 * 36 + 128 * 36) * 4;  // 110592
    constexpr int SM_NN = S * (128 * 36 + 32 * 136) * 4;  // 107520
    cudaFuncSetAttribute(gemm_tc<0, 0, false>,
                         cudaFuncAttributeMaxDynamicSharedMemorySize, SM_NT);
    cudaFuncSetAttribute(gemm_tc<1, 0, true>,
                         cudaFuncAttributeMaxDynamicSharedMemorySize, SM_NN);
    cudaFuncSetAttribute(gemm_tc<2, 1, true>,
                         cudaFuncAttributeMaxDynamicSharedMemorySize, SM_NN);
    cudaFuncSetAttribute(gemm_tc<1, 2, false>,
                         cudaFuncAttributeMaxDynamicSharedMemorySize, SM_NN);

    // pre-round constant operands
    round_kernel<<<1024, 256>>>(inputs, inr, BB * LL * DD);
    round_kernel<<<128, 256>>>(pool_w1, w1r, DD * DD);
    wtrans_kernel<<<256, 256>>>(conv_w);

    // ---- hop 0: raw similarity on inputs ----
    gemm_tc<0, 0, false><<<dim3(LL / 128, LL / 128, BB), 256, SM_NT>>>(
        inr, inr, scores, nullptr, nullptr,
        DD, DD, DD, LL, (long)LL * DD, (long)LL * DD, (long)LL * LL);
    softmask_kernel<<<BB * LL / 8, 256>>>(scores, mask);
    gemm_tc<1, 0, true><<<dim3(DD / 128, LL / 128, BB), 256, SM_NN>>>(
        scores, inr, result, resultr, nullptr,
        LL, LL, DD, NH * DD, (long)LL * LL, (long)LL * DD, (long)LL * NH * DD);

    // ---- hops 1..3 (rounded conv buffers ping-pong: never read+write same) ----
    const float* curR = inr;
    for (int h = 0; h < HOPS; h++) {
        float* cdst  = (h == HOPS - 1) ? out : conv;            // fp32 conv output
        float* crDst = (h & 1) ? convr1 : convr0;               // rounded conv output
        gemm_tc<2, 1, true><<<dim3(DD / 128, LL / 128, BB), 256, SM_NN>>>(
            curR, wt + (long)h * 3 * DD * DD, cdst, crDst, conv_b + h * DD,
            3 * DD, 0, DD, DD, (long)LL * DD, 0L, (long)LL * DD);
        l2norm_kernel<<<BB * LL / 8, 256>>>(cdst, nrm);
        gemm_tc<0, 0, false><<<dim3(LL / 128, LL / 128, BB), 256, SM_NT>>>(
            nrm, nrm, scores, nullptr, nullptr,
            DD, DD, DD, LL, (long)LL * DD, (long)LL * DD, (long)LL * LL);
        softmask_kernel<<<BB * LL / 8, 256>>>(scores, mask);
        gemm_tc<1, 0, true><<<dim3(DD / 128, LL / 128, BB), 256, SM_NN>>>(
            scores, crDst, result + (long)(h + 1) * DD, resultr + (long)(h + 1) * DD, nullptr,
            LL, LL, DD, NH * DD, (long)LL * LL, (long)LL * DD, (long)LL * NH * DD);
        curR = crDst;
    }

    // pooling: hidden = tanh(result @ W1 + b1)
    gemm_tc<1, 2, false><<<dim3(DD / 128, (BB * LL * NH) / 128, 1), 256, SM_NN>>>(
        resultr, w1r, hidden, nullptr, pool_b1,
        DD, DD, DD, DD, 0L, 0L, 0L);

    // output #2: weighted
    pool_finalize_kernel<<<BB * LL / 8, 256>>>(pool_w2, pool_b2, out + (long)BB * LL * DD);
}

// round 6
// speedup vs baseline: 3.3836x; 1.0455x over previous
#include <cuda_runtime.h>
#include <math.h>

#define BB 16
#define LL 512
#define DD 768
#define HOPS 3
#define NH (HOPS + 1)

// ---------------- scratch (static device globals; no allocs) ----------------
__device__ __align__(16) float g_convr0[(long)BB * LL * DD];        // rounded conv (ping)
__device__ __align__(16) float g_convr1[(long)BB * LL * DD];        // rounded conv (pong)
__device__ __align__(16) float g_norm[(long)BB * LL * DD];          // l2norm(conv), rounded
__device__ __align__(16) float g_scores[(long)BB * LL * LL];        // attention matrix
__device__ __align__(16) float g_resultr[(long)BB * LL * NH * DD];  // rounded [B,L,4,D]
__device__ __align__(16) float g_wt[(long)HOPS * 3 * DD * DD];      // conv weights K-major rounded
__device__ __align__(16) float g_inr[(long)BB * LL * DD];           // inputs tf32-rounded
__device__ __align__(16) float g_w1r[(long)DD * DD];                // pool_w1 rounded
__device__ __align__(16) float g_pp[(long)BB * LL * NH * 12];       // pool-score partials

// ---- fp32 -> tf32 round-to-nearest (bias-free) ----
__device__ __forceinline__ float f2tf32(float x) {
    unsigned y;
    asm("cvt.rna.tf32.f32 %0, %1;" : "=r"(y) : "f"(x));
    return __uint_as_float(y);
}

__device__ __forceinline__ void mma_tf32(float c[4],
                                         unsigned a0, unsigned a1, unsigned a2, unsigned a3,
                                         unsigned b0, unsigned b1) {
    asm volatile(
        "mma.sync.aligned.m16n8k8.row.col.f32.tf32.tf32.f32 "
        "{%0,%1,%2,%3}, {%4,%5,%6,%7}, {%8,%9}, {%0,%1,%2,%3};"
        : "+f"(c[0]), "+f"(c[1]), "+f"(c[2]), "+f"(c[3])
        : "r"(a0), "r"(a1), "r"(a2), "r"(a3), "r"(b0), "r"(b1));
}

__device__ __forceinline__ void cp16(void* smem_dst, const void* gsrc) {
    unsigned d = (unsigned)__cvta_generic_to_shared(smem_dst);
    asm volatile("cp.async.cg.shared.global [%0], [%1], 16;" :: "r"(d), "l"(gsrc));
}
__device__ __forceinline__ void cp16z(void* smem_dst, const void* gsrc, bool ok) {
    unsigned d = (unsigned)__cvta_generic_to_shared(smem_dst);
    int sz = ok ? 16 : 0;
    asm volatile("cp.async.cg.shared.global [%0], [%1], 16, %2;" :: "r"(d), "l"(gsrc), "r"(sz));
}
__device__ __forceinline__ void cp_commit() {
    asm volatile("cp.async.commit_group;");
}
template <int N>
__device__ __forceinline__ void cp_wait() {
    asm volatile("cp.async.wait_group %0;" :: "n"(N));
}

// ---------------- tensor-core 128x128x32 GEMM, 4 warps of 64x64 -------------
// Operands pre-rounded to tf32. C[M,N] = A[M,K] * B.
// MODE 0: NT — B is [N,K] row-major.
// MODE 1: NN — B is [K,N] row-major.
// MODE 2: NN-conv — A is implicit im2col of a [L,D] sequence
//         (token = row - 1 + k/768, zero-padded at ends), K = 3*768.
// EPI 0: none.  EPI 1: relu(x + bias[n]).
// EPI 3: pool — tanh(x + bias[n]), partial dot with w2 -> g_pp (no C store).
// OUT 0: store fp32 C.  OUT 1: store tf32-rounded C.  OUT 2: fp32 C + rounded Caux.
template <int MODE, int EPI, int OUT>
__global__ __launch_bounds__(128, 2) void gemm_tc(
    const float* __restrict__ A, const float* __restrict__ Bm,
    float* __restrict__ C, float* __restrict__ Caux,
    const float* __restrict__ bias, const float* __restrict__ w2,
    float* __restrict__ pp,
    int K, int lda, int ldb, int ldc,
    long sA, long sB, long sC)
{
    constexpr int BM = 128, BN = 128, BK = 32, S = 3;
    constexpr int BKP = 36;   // 32 + 4 pad
    constexpr int BNP = 136;  // 128 + 8 pad
    constexpr bool BT = (MODE == 0);

    extern __shared__ float sm[];
    float* Asm = sm;                          // [S][BM][BKP]
    float* Bsm = sm + (long)S * BM * BKP;     // NT: [S][BN][BKP] ; NN: [S][BK][BNP]

    const int tid = threadIdx.x;
    const int bx = blockIdx.x, by = blockIdx.y, bz = blockIdx.z;

    const float* Ab = A + (long)bz * sA + (MODE == 2 ? 0L : (long)by * BM * lda);
    const float* Bb;
    if (BT) Bb = Bm + (long)bz * sB + (long)bx * BN * ldb;
    else    Bb = Bm + (long)bz * sB + bx * BN;

    const int wid  = tid >> 5;
    const int lane = tid & 31;
    const int wm = (wid & 1) * 64;   // 2 warps in M
    const int wn = (wid >> 1) * 64;  // 2 warps in N
    const int gid = lane >> 2;       // 0..7
    const int tig = lane & 3;        // 0..3

    float acc[4][8][4];
#pragma unroll
    for (int mt = 0; mt < 4; mt++)
#pragma unroll
        for (int nt = 0; nt < 8; nt++)
#pragma unroll
            for (int r = 0; r < 4; r++) acc[mt][nt][r] = 0.f;

    const int KT = K / BK;

    auto issue_copy = [&](int kt, int s) {
        const int k0 = kt * BK;
        float* As = Asm + (long)s * BM * BKP;
        // A tile: 128x32 floats = 1024 16B-chunks, 8 per thread
#pragma unroll
        for (int t = 0; t < 8; t++) {
            int id  = tid + t * 128;
            int row = id >> 3;          // 0..127
            int c4  = (id & 7) * 4;     // 0..28
            if (MODE == 2) {
                int k   = k0 + c4;
                int sub = (k >= 1536) ? 2 : (k >= 768 ? 1 : 0);
                int tok = by * BM + row - 1 + sub;
                int d   = k - sub * 768;
                bool ok = ((unsigned)tok < (unsigned)LL);
                int tc  = ok ? tok : 0;
                cp16z(As + (long)row * BKP + c4, Ab + (long)tc * DD + d, ok);
            } else {
                cp16(As + (long)row * BKP + c4, Ab + (long)row * lda + k0 + c4);
            }
        }
        if (BT) {
            float* Bs = Bsm + (long)s * BN * BKP;
#pragma unroll
            for (int t = 0; t < 8; t++) {
                int id  = tid + t * 128;
                int row = id >> 3;
                int c4  = (id & 7) * 4;
                cp16(Bs + (long)row * BKP + c4, Bb + (long)row * ldb + k0 + c4);
            }
        } else {
            float* Bs = Bsm + (long)s * BK * BNP;
#pragma unroll
            for (int t = 0; t < 8; t++) {
                int id  = tid + t * 128;
                int row = id >> 5;          // k 0..31
                int c4  = (id & 31) * 4;    // n
                cp16(Bs + (long)row * BNP + c4, Bb + (long)(k0 + row) * ldb + c4);
            }
        }
        cp_commit();
    };

#pragma unroll
    for (int s = 0; s < S - 1; s++) issue_copy(s, s);

    for (int kt = 0; kt < KT; kt++) {
        const int s = kt % S;
        cp_wait<S - 2>();
        __syncthreads();

        const int pre = kt + S - 1;
        if (pre < KT) issue_copy(pre, pre % S);

        const float* As = Asm + (long)s * BM * BKP;
        const float* BsNT = Bsm + (long)s * BN * BKP;
        const float* BsNN = Bsm + (long)s * BK * BNP;

#pragma unroll
        for (int ks = 0; ks < BK; ks += 8) {
            unsigned bf[8][2];
#pragma unroll
            for (int nt = 0; nt < 8; nt++) {
                const int n = wn + nt * 8 + gid;
                if (BT) {
                    bf[nt][0] = __float_as_uint(BsNT[(long)n * BKP + ks + tig]);
                    bf[nt][1] = __float_as_uint(BsNT[(long)n * BKP + ks + tig + 4]);
                } else {
                    bf[nt][0] = __float_as_uint(BsNN[(long)(ks + tig) * BNP + n]);
                    bf[nt][1] = __float_as_uint(BsNN[(long)(ks + tig + 4) * BNP + n]);
                }
            }
#pragma unroll
            for (int mt = 0; mt < 4; mt++) {
                const int m = wm + mt * 16 + gid;
                unsigned a0 = __float_as_uint(As[(long)m * BKP + ks + tig]);
                unsigned a1 = __float_as_uint(As[(long)(m + 8) * BKP + ks + tig]);
                unsigned a2 = __float_as_uint(As[(long)m * BKP + ks + tig + 4]);
                unsigned a3 = __float_as_uint(As[(long)(m + 8) * BKP + ks + tig + 4]);
#pragma unroll
                for (int nt = 0; nt < 8; nt++)
                    mma_tf32(acc[mt][nt], a0, a1, a2, a3, bf[nt][0], bf[nt][1]);
            }
        }
    }

    if (EPI == 3) {
        // pool: part[mt][half] = sum over this warp's 64 cols of tanh(v+b1)*w2
        float part[4][2];
#pragma unroll
        for (int mt = 0; mt < 4; mt++) { part[mt][0] = 0.f; part[mt][1] = 0.f; }
#pragma unroll
        for (int nt = 0; nt < 8; nt++) {
            const int c = bx * BN + wn + nt * 8 + 2 * tig;
            float b0 = bias[c], b1 = bias[c + 1];
            float w0 = w2[c],   w1 = w2[c + 1];
#pragma unroll
            for (int mt = 0; mt < 4; mt++) {
                part[mt][0] += tanhf(acc[mt][nt][0] + b0) * w0
                             + tanhf(acc[mt][nt][1] + b1) * w1;
                part[mt][1] += tanhf(acc[mt][nt][2] + b0) * w0
                             + tanhf(acc[mt][nt][3] + b1) * w1;
            }
        }
        // reduce across tig (lanes sharing gid)
#pragma unroll
        for (int o = 1; o <= 2; o <<= 1)
#pragma unroll
            for (int mt = 0; mt < 4; mt++) {
                part[mt][0] += __shfl_xor_sync(0xffffffffu, part[mt][0], o);
                part[mt][1] += __shfl_xor_sync(0xffffffffu, part[mt][1], o);
            }
        if (tig == 0) {
#pragma unroll
            for (int mt = 0; mt < 4; mt++) {
#pragma unroll
                for (int half = 0; half < 2; half++) {
                    int row = by * BM + wm + mt * 16 + gid + half * 8;
                    pp[((long)row * 6 + bx) * 2 + (wid >> 1)] = part[mt][half];
                }
            }
        }
        return;
    }

    float* Cb = C + (long)bz * sC + (long)(by * BM) * ldc + bx * BN;
    float* Xb = (OUT == 2) ? (Caux + (long)bz * sC + (long)(by * BM) * ldc + bx * BN) : nullptr;
#pragma unroll
    for (int nt = 0; nt < 8; nt++) {
        const int c = wn + nt * 8 + 2 * tig;
        float b0 = 0.f, b1 = 0.f;
        if (EPI == 1) {
            b0 = bias[bx * BN + c];
            b1 = bias[bx * BN + c + 1];
        }
#pragma unroll
        for (int mt = 0; mt < 4; mt++) {
            const int r0 = wm + mt * 16 + gid;
            float v0 = acc[mt][nt][0], v1 = acc[mt][nt][1];
            float v2 = acc[mt][nt][2], v3 = acc[mt][nt][3];
            if (EPI == 1) {
                v0 = fmaxf(v0 + b0, 0.f); v1 = fmaxf(v1 + b1, 0.f);
                v2 = fmaxf(v2 + b0, 0.f); v3 = fmaxf(v3 + b1, 0.f);
            }
            if (OUT == 1) {
                *reinterpret_cast<float2*>(Cb + (long)r0 * ldc + c) =
                    make_float2(f2tf32(v0), f2tf32(v1));
                *reinterpret_cast<float2*>(Cb + (long)(r0 + 8) * ldc + c) =
                    make_float2(f2tf32(v2), f2tf32(v3));
            } else {
                *reinterpret_cast<float2*>(Cb + (long)r0 * ldc + c)       = make_float2(v0, v1);
                *reinterpret_cast<float2*>(Cb + (long)(r0 + 8) * ldc + c) = make_float2(v2, v3);
                if (OUT == 2) {
                    *reinterpret_cast<float2*>(Xb + (long)r0 * ldc + c) =
                        make_float2(f2tf32(v0), f2tf32(v1));
                    *reinterpret_cast<float2*>(Xb + (long)(r0 + 8) * ldc + c) =
                        make_float2(f2tf32(v2), f2tf32(v3));
                }
            }
        }
    }
}

// ---------------- tf32-round a buffer (float4 granularity) ------------------
__global__ void round_kernel(const float* __restrict__ src, float* __restrict__ dst, int n)
{
    for (int i = blockIdx.x * blockDim.x + threadIdx.x; i * 4 < n;
         i += gridDim.x * blockDim.x) {
        float4 v = *reinterpret_cast<const float4*>(src + i * 4);
        v.x = f2tf32(v.x); v.y = f2tf32(v.y); v.z = f2tf32(v.z); v.w = f2tf32(v.w);
        *reinterpret_cast<float4*>(dst + i * 4) = v;
    }
}

// ---------------- masked softmax over rows of [B,L,L]; rounded output -------
__global__ void softmask_kernel(float* __restrict__ S, const float* __restrict__ mask)
{
    int gw   = (blockIdx.x * blockDim.x + threadIdx.x) >> 5;
    int lane = threadIdx.x & 31;
    if (gw >= BB * LL) return;
    int b = gw / LL;
    int l = gw - b * LL;
    float* row = S + (long)gw * LL;
    const float* mk = mask + (long)b * LL;

    float v[16];
    float mx = -1e30f;
#pragma unroll
    for (int t = 0; t < 16; t++) {
        v[t] = row[lane + t * 32];
        mx = fmaxf(mx, v[t]);
    }
#pragma unroll
    for (int o = 16; o; o >>= 1) mx = fmaxf(mx, __shfl_xor_sync(0xffffffffu, mx, o));

    float sum = 0.f;
#pragma unroll
    for (int t = 0; t < 16; t++) {
        float e = __expf(v[t] - mx) * mk[lane + t * 32];
        v[t] = e;
        sum += e;
    }
#pragma unroll
    for (int o = 16; o; o >>= 1) sum += __shfl_xor_sync(0xffffffffu, sum, o);

    float scale = mk[l] / (sum + 1e-10f);
#pragma unroll
    for (int t = 0; t < 16; t++) row[lane + t * 32] = f2tf32(v[t] * scale);
}

// ---------------- L2 normalize rows of [B*L, D]; rounded output -------------
__global__ void l2norm_kernel(const float* __restrict__ X, float* __restrict__ Y)
{
    int gw   = (blockIdx.x * blockDim.x + threadIdx.x) >> 5;
    int lane = threadIdx.x & 31;
    if (gw >= BB * LL) return;
    const float* x = X + (long)gw * DD;
    float* y = Y + (long)gw * DD;
    float ss = 0.f;
#pragma unroll
    for (int t = 0; t < 24; t++) {
        float v = x[lane + t * 32];
        ss += v * v;
    }
#pragma unroll
    for (int o = 16; o; o >>= 1) ss += __shfl_xor_sync(0xffffffffu, ss, o);
    float scale = 1.f / fmaxf(sqrtf(ss), 1e-12f);
#pragma unroll
    for (int t = 0; t < 24; t++) y[lane + t * 32] = f2tf32(x[lane + t * 32] * scale);
}

// ------- conv weight transpose: W[h][o][i][k] -> Wt[h][k*D+i][o]; rounded ----
__global__ void wtrans_kernel(const float* __restrict__ W)
{
    const long n = (long)HOPS * 3 * DD * DD;
    for (long i = blockIdx.x * (long)blockDim.x + threadIdx.x; i < n;
         i += (long)gridDim.x * blockDim.x) {
        long h    = i / (3L * DD * DD);
        long rem  = i - h * 3L * DD * DD;
        long k    = rem / ((long)DD * DD);
        long rem2 = rem - k * (long)DD * DD;
        long ii   = rem2 / DD;
        long o    = rem2 - ii * DD;
        g_wt[i] = f2tf32(W[((h * DD + o) * DD + ii) * 3 + k]);
    }
}

// ---------------- pooling tail: read partial scores, softmax, weighted ------
__global__ void pool_finalize_kernel(const float* __restrict__ b2,
                                     float* __restrict__ out)
{
    int gw   = (blockIdx.x * blockDim.x + threadIdx.x) >> 5;
    int lane = threadIdx.x & 31;
    if (gw >= BB * LL) return;
    const float* res = g_resultr + (long)gw * NH * DD;

    float s[NH];
#pragma unroll
    for (int h = 0; h < NH; h++) {
        float p = (lane < 12) ? g_pp[(long)(gw * NH + h) * 12 + lane] : 0.f;
#pragma unroll
        for (int o = 16; o; o >>= 1) p += __shfl_xor_sync(0xffffffffu, p, o);
        s[h] = p + b2[0];
    }
    float mx = fmaxf(fmaxf(s[0], s[1]), fmaxf(s[2], s[3]));
    float e0 = __expf(s[0] - mx), e1 = __expf(s[1] - mx);
    float e2 = __expf(s[2] - mx), e3 = __expf(s[3] - mx);
    float inv = 1.f / (e0 + e1 + e2 + e3);
    e0 *= inv; e1 *= inv; e2 *= inv; e3 *= inv;

    float* o = out + (long)gw * DD;
#pragma unroll
    for (int t = 0; t < 24; t++) {
        int d = lane + t * 32;
        o[d] = e0 * res[d] + e1 * res[DD + d] + e2 * res[2 * DD + d] + e3 * res[3 * DD + d];
    }
}

// ---------------- orchestration ---------------------------------------------
extern "C" void kernel_launch(void* const* d_in, const int* in_sizes, int n_in,
                              void* d_out, int out_size)
{
    (void)in_sizes; (void)n_in; (void)out_size;
    const float* inputs  = (const float*)d_in[0];
    const float* mask    = (const float*)d_in[1];
    const float* conv_w  = (const float*)d_in[2];
    const float* conv_b  = (const float*)d_in[3];
    const float* pool_w1 = (const float*)d_in[4];
    const float* pool_b1 = (const float*)d_in[5];
    const float* pool_w2 = (const float*)d_in[6];
    const float* pool_b2 = (const float*)d_in[7];
    float* out = (float*)d_out;

    float *convr0, *convr1, *nrm, *scores, *resultr, *wt, *inr, *w1r, *pp;
    cudaGetSymbolAddress((void**)&convr0,  g_convr0);
    cudaGetSymbolAddress((void**)&convr1,  g_convr1);
    cudaGetSymbolAddress((void**)&nrm,     g_norm);
    cudaGetSymbolAddress((void**)&scores,  g_scores);
    cudaGetSymbolAddress((void**)&resultr, g_resultr);
    cudaGetSymbolAddress((void**)&wt,      g_wt);
    cudaGetSymbolAddress((void**)&inr,     g_inr);
    cudaGetSymbolAddress((void**)&w1r,     g_w1r);
    cudaGetSymbolAddress((void**)&pp,      g_pp);

    constexpr int S = 3;
    constexpr int SM_NT = S * (128 * 36 + 128 * 36) * 4;  // 110592
    constexpr int SM_NN = S * (128 * 36 + 32 * 136) * 4;  // 107520
    cudaFuncSetAttribute(gemm_tc<0, 0, 0>,
                         cudaFuncAttributeMaxDynamicSharedMemorySize, SM_NT);
    cudaFuncSetAttribute(gemm_tc<1, 0, 1>,
                         cudaFuncAttributeMaxDynamicSharedMemorySize, SM_NN);
    cudaFuncSetAttribute(gemm_tc<2, 1, 1>,
                         cudaFuncAttributeMaxDynamicSharedMemorySize, SM_NN);
    cudaFuncSetAttribute(gemm_tc<2, 1, 2>,
                         cudaFuncAttributeMaxDynamicSharedMemorySize, SM_NN);
    cudaFuncSetAttribute(gemm_tc<1, 3, 0>,
                         cudaFuncAttributeMaxDynamicSharedMemorySize, SM_NN);

    // pre-round constant operands
    round_kernel<<<1024, 256>>>(inputs, inr, BB * LL * DD);
    round_kernel<<<128, 256>>>(pool_w1, w1r, DD * DD);
    wtrans_kernel<<<256, 256>>>(conv_w);

    // ---- hop 0: raw similarity on inputs ----
    gemm_tc<0, 0, 0><<<dim3(LL / 128, LL / 128, BB), 128, SM_NT>>>(
        inr, inr, scores, nullptr, nullptr, nullptr, nullptr,
        DD, DD, DD, LL, (long)LL * DD, (long)LL * DD, (long)LL * LL);
    softmask_kernel<<<BB * LL / 8, 256>>>(scores, mask);
    gemm_tc<1, 0, 1><<<dim3(DD / 128, LL / 128, BB), 128, SM_NN>>>(
        scores, inr, resultr, nullptr, nullptr, nullptr, nullptr,
        LL, LL, DD, NH * DD, (long)LL * LL, (long)LL * DD, (long)LL * NH * DD);

    // ---- hops 1..3 ----
    const float* curR = inr;
    for (int h = 0; h < HOPS; h++) {
        float* crDst = (h & 1) ? convr1 : convr0;
        if (h == HOPS - 1) {
            // last conv: fp32 straight to d_out + rounded copy
            gemm_tc<2, 1, 2><<<dim3(DD / 128, LL / 128, BB), 128, SM_NN>>>(
                curR, wt + (long)h * 3 * DD * DD, out, crDst, conv_b + h * DD, nullptr, nullptr,
                3 * DD, 0, DD, DD, (long)LL * DD, 0L, (long)LL * DD);
        } else {
            gemm_tc<2, 1, 1><<<dim3(DD / 128, LL / 128, BB), 128, SM_NN>>>(
                curR, wt + (long)h * 3 * DD * DD, crDst, nullptr, conv_b + h * DD, nullptr, nullptr,
                3 * DD, 0, DD, DD, (long)LL * DD, 0L, (long)LL * DD);
        }
        l2norm_kernel<<<BB * LL / 8, 256>>>(crDst, nrm);
        gemm_tc<0, 0, 0><<<dim3(LL / 128, LL / 128, BB), 128, SM_NT>>>(
            nrm, nrm, scores, nullptr, nullptr, nullptr, nullptr,
            DD, DD, DD, LL, (long)LL * DD, (long)LL * DD, (long)LL * LL);
        softmask_kernel<<<BB * LL / 8, 256>>>(scores, mask);
        gemm_tc<1, 0, 1><<<dim3(DD / 128, LL / 128, BB), 128, SM_NN>>>(
            scores, crDst, resultr + (long)(h + 1) * DD, nullptr, nullptr, nullptr, nullptr,
            LL, LL, DD, NH * DD, (long)LL * LL, (long)LL * DD, (long)LL * NH * DD);
        curR = crDst;
    }

    // pooling: fused tanh(result@W1+b1)·w2 partials (no hidden buffer)
    gemm_tc<1, 3, 0><<<dim3(DD / 128, (BB * LL * NH) / 128, 1), 128, SM_NN>>>(
        resultr, w1r, nullptr, nullptr, pool_b1, pool_w2, pp,
        DD, DD, DD, DD, 0L, 0L, 0L);

    // output #2: weighted
    pool_finalize_kernel<<<BB * LL / 8, 256>>>(pool_b2, out + (long)BB * LL * DD);
}

// round 7
// speedup vs baseline: 5.7687x; 1.7049x over previous
#include <cuda_runtime.h>
#include <cuda_fp16.h>
#include <math.h>

#define BB 16
#define LL 512
#define DD 768
#define HOPS 3
#define NH (HOPS + 1)

// ---------------- scratch (static device globals; no allocs) ----------------
__device__ __align__(16) __half g_inrH[(long)BB * LL * DD];     // inputs fp16, token-major
__device__ __align__(16) __half g_inrT[(long)BB * DD * LL];     // inputs fp16, d-major (V^T)
__device__ __align__(16) __half g_convrH0[(long)BB * LL * DD];  // conv fp16 (ping)
__device__ __align__(16) __half g_convrH1[(long)BB * LL * DD];  // conv fp16 (pong)
__device__ __align__(16) __half g_convrT[(long)BB * DD * LL];   // conv fp16 transposed
__device__ __align__(16) __half g_nrm[(long)BB * LL * DD];      // l2norm fp16
__device__ __align__(16) float  g_scores[(long)BB * LL * LL];   // pre-softmax scores fp32
__device__ __align__(16) __half g_scoresH[(long)BB * LL * LL];  // post-softmax fp16
__device__ __align__(16) __half g_resultrH[(long)BB * LL * NH * DD]; // [B,L,4,D] fp16
__device__ __align__(16) __half g_wtH[(long)HOPS * DD * 3 * DD];     // conv W [h][o][k] K-major
__device__ __align__(16) __half g_w1T[(long)DD * DD];                // pool W1^T [e][d]
__device__ __align__(16) float  g_pp[(long)BB * LL * NH * 24];       // pool-score partials

// ---------------- mma m16n8k16 fp16 -> fp32 ---------------------------------
__device__ __forceinline__ void mma_f16(float c[4],
                                        unsigned a0, unsigned a1, unsigned a2, unsigned a3,
                                        unsigned b0, unsigned b1) {
    asm volatile(
        "mma.sync.aligned.m16n8k16.row.col.f32.f16.f16.f32 "
        "{%0,%1,%2,%3}, {%4,%5,%6,%7}, {%8,%9}, {%0,%1,%2,%3};"
        : "+f"(c[0]), "+f"(c[1]), "+f"(c[2]), "+f"(c[3])
        : "r"(a0), "r"(a1), "r"(a2), "r"(a3), "r"(b0), "r"(b1));
}

__device__ __forceinline__ void cp16(void* smem_dst, const void* gsrc) {
    unsigned d = (unsigned)__cvta_generic_to_shared(smem_dst);
    asm volatile("cp.async.cg.shared.global [%0], [%1], 16;" :: "r"(d), "l"(gsrc));
}
__device__ __forceinline__ void cp16z(void* smem_dst, const void* gsrc, bool ok) {
    unsigned d = (unsigned)__cvta_generic_to_shared(smem_dst);
    int sz = ok ? 16 : 0;
    asm volatile("cp.async.cg.shared.global [%0], [%1], 16, %2;" :: "r"(d), "l"(gsrc), "r"(sz));
}
__device__ __forceinline__ void cp_commit() { asm volatile("cp.async.commit_group;"); }
template <int N>
__device__ __forceinline__ void cp_wait() { asm volatile("cp.async.wait_group %0;" :: "n"(N)); }

// ---------------- fp16 NT GEMM: 128x128x64 tiles, 3-stage cp.async ----------
// C[M,N] = A[M,K] * B[N,K]^T, both fp16 K-major. 256 thr, 8 warps of 64x32.
// MODE 0: normal. MODE 2: A is implicit im2col of token-major [L,D] fp16
//         (token = by*128+row-1+k/768, zero-padded at ends), K = 3*768.
// EPI 0: none. EPI 1: relu(x+bias[n]). EPI 3: pool partials (tanh(x+b1)*w2).
// OUT 0: store fp32 C. OUT 1: store fp16 C16. OUT 2: fp32 C + fp16 Caux.
template <int MODE, int EPI, int OUT>
__global__ __launch_bounds__(256, 2) void gemm_h(
    const __half* __restrict__ A, const __half* __restrict__ Bm,
    float* __restrict__ C, __half* __restrict__ C16, __half* __restrict__ Caux,
    const float* __restrict__ bias, const float* __restrict__ w2,
    float* __restrict__ pp,
    int K, int lda, int ldb, int ldc,
    long sA, long sB, long sC)
{
    constexpr int BM = 128, BN = 128, BK = 64, S = 3;
    constexpr int BKP = 72;  // 64 + 8 halves pad (144B rows; fragment LDS conflict-free)

    extern __shared__ __half sh[];
    __half* Asm = sh;                         // [S][BM][BKP]
    __half* Bsm = sh + (long)S * BM * BKP;    // [S][BN][BKP]

    const int tid = threadIdx.x;
    const int bx = blockIdx.x, by = blockIdx.y, bz = blockIdx.z;

    const __half* Ab = A + (long)bz * sA + (MODE == 2 ? 0L : (long)by * BM * lda);
    const __half* Bb = Bm + (long)bz * sB + (long)bx * BN * ldb;

    const int wid  = tid >> 5;
    const int lane = tid & 31;
    const int wm = (wid & 1) * 64;    // 2 warps in M
    const int wn = (wid >> 1) * 32;   // 4 warps in N
    const int gid = lane >> 2;        // 0..7
    const int tig = lane & 3;         // 0..3

    float acc[4][4][4];
#pragma unroll
    for (int mt = 0; mt < 4; mt++)
#pragma unroll
        for (int nt = 0; nt < 4; nt++)
#pragma unroll
            for (int r = 0; r < 4; r++) acc[mt][nt][r] = 0.f;

    const int KT = K / BK;

    auto issue_copy = [&](int kt, int s) {
        const int k0 = kt * BK;
        __half* As = Asm + (long)s * BM * BKP;
        // A: 128 rows x 64 halves = 1024 16B-chunks (8 halves each), 4/thread
#pragma unroll
        for (int t = 0; t < 4; t++) {
            int id  = tid + t * 256;
            int row = id >> 3;          // 0..127
            int c8  = (id & 7) * 8;     // 0..56
            if (MODE == 2) {
                int k   = k0 + c8;
                int sub = (k >= 1536) ? 2 : (k >= 768 ? 1 : 0);
                int tok = by * BM + row - 1 + sub;
                int d   = k - sub * 768;
                bool ok = ((unsigned)tok < (unsigned)LL);
                int tc  = ok ? tok : 0;
                cp16z(As + (long)row * BKP + c8, Ab + (long)tc * DD + d, ok);
            } else {
                cp16(As + (long)row * BKP + c8, Ab + (long)row * lda + k0 + c8);
            }
        }
        __half* Bs = Bsm + (long)s * BN * BKP;
#pragma unroll
        for (int t = 0; t < 4; t++) {
            int id  = tid + t * 256;
            int row = id >> 3;
            int c8  = (id & 7) * 8;
            cp16(Bs + (long)row * BKP + c8, Bb + (long)row * ldb + k0 + c8);
        }
        cp_commit();
    };

#pragma unroll
    for (int s = 0; s < S - 1; s++) issue_copy(s, s);

    for (int kt = 0; kt < KT; kt++) {
        const int s = kt % S;
        cp_wait<S - 2>();
        __syncthreads();

        const int pre = kt + S - 1;
        if (pre < KT) issue_copy(pre, pre % S);

        const __half* As = Asm + (long)s * BM * BKP;
        const __half* Bs = Bsm + (long)s * BN * BKP;

#pragma unroll
        for (int ks = 0; ks < BK; ks += 16) {
            unsigned bf[4][2];
#pragma unroll
            for (int nt = 0; nt < 4; nt++) {
                const int n = wn + nt * 8 + gid;
                bf[nt][0] = *reinterpret_cast<const unsigned*>(&Bs[(long)n * BKP + ks + 2 * tig]);
                bf[nt][1] = *reinterpret_cast<const unsigned*>(&Bs[(long)n * BKP + ks + 2 * tig + 8]);
            }
#pragma unroll
            for (int mt = 0; mt < 4; mt++) {
                const int m = wm + mt * 16 + gid;
                unsigned a0 = *reinterpret_cast<const unsigned*>(&As[(long)m * BKP + ks + 2 * tig]);
                unsigned a1 = *reinterpret_cast<const unsigned*>(&As[(long)(m + 8) * BKP + ks + 2 * tig]);
                unsigned a2 = *reinterpret_cast<const unsigned*>(&As[(long)m * BKP + ks + 2 * tig + 8]);
                unsigned a3 = *reinterpret_cast<const unsigned*>(&As[(long)(m + 8) * BKP + ks + 2 * tig + 8]);
#pragma unroll
                for (int nt = 0; nt < 4; nt++)
                    mma_f16(acc[mt][nt], a0, a1, a2, a3, bf[nt][0], bf[nt][1]);
            }
        }
    }

    if (EPI == 3) {
        float part[4][2];
#pragma unroll
        for (int mt = 0; mt < 4; mt++) { part[mt][0] = 0.f; part[mt][1] = 0.f; }
#pragma unroll
        for (int nt = 0; nt < 4; nt++) {
            const int c = bx * BN + wn + nt * 8 + 2 * tig;
            float b0 = bias[c], b1 = bias[c + 1];
            float w0 = w2[c],   w1 = w2[c + 1];
#pragma unroll
            for (int mt = 0; mt < 4; mt++) {
                part[mt][0] += tanhf(acc[mt][nt][0] + b0) * w0
                             + tanhf(acc[mt][nt][1] + b1) * w1;
                part[mt][1] += tanhf(acc[mt][nt][2] + b0) * w0
                             + tanhf(acc[mt][nt][3] + b1) * w1;
            }
        }
#pragma unroll
        for (int o = 1; o <= 2; o <<= 1)
#pragma unroll
            for (int mt = 0; mt < 4; mt++) {
                part[mt][0] += __shfl_xor_sync(0xffffffffu, part[mt][0], o);
                part[mt][1] += __shfl_xor_sync(0xffffffffu, part[mt][1], o);
            }
        if (tig == 0) {
#pragma unroll
            for (int mt = 0; mt < 4; mt++)
#pragma unroll
                for (int half = 0; half < 2; half++) {
                    int row = by * BM + wm + mt * 16 + gid + half * 8;
                    pp[((long)row * 6 + bx) * 4 + (wid >> 1)] = part[mt][half];
                }
        }
        return;
    }

    float*  Cf = (OUT != 1) ? (C + (long)bz * sC + (long)(by * BM) * ldc + bx * BN) : nullptr;
    __half* Ch = (OUT == 1) ? (C16 + (long)bz * sC + (long)(by * BM) * ldc + bx * BN)
               : (OUT == 2) ? (Caux + (long)bz * sC + (long)(by * BM) * ldc + bx * BN) : nullptr;
#pragma unroll
    for (int nt = 0; nt < 4; nt++) {
        const int c = wn + nt * 8 + 2 * tig;
        float b0 = 0.f, b1 = 0.f;
        if (EPI == 1) {
            b0 = bias[bx * BN + c];
            b1 = bias[bx * BN + c + 1];
        }
#pragma unroll
        for (int mt = 0; mt < 4; mt++) {
            const int r0 = wm + mt * 16 + gid;
            float v0 = acc[mt][nt][0], v1 = acc[mt][nt][1];
            float v2 = acc[mt][nt][2], v3 = acc[mt][nt][3];
            if (EPI == 1) {
                v0 = fmaxf(v0 + b0, 0.f); v1 = fmaxf(v1 + b1, 0.f);
                v2 = fmaxf(v2 + b0, 0.f); v3 = fmaxf(v3 + b1, 0.f);
            }
            if (OUT != 1) {
                *reinterpret_cast<float2*>(Cf + (long)r0 * ldc + c)       = make_float2(v0, v1);
                *reinterpret_cast<float2*>(Cf + (long)(r0 + 8) * ldc + c) = make_float2(v2, v3);
            }
            if (OUT != 0) {
                *reinterpret_cast<__half2*>(Ch + (long)r0 * ldc + c)       = __floats2half2_rn(v0, v1);
                *reinterpret_cast<__half2*>(Ch + (long)(r0 + 8) * ldc + c) = __floats2half2_rn(v2, v3);
            }
        }
    }
}

// ---------------- inputs fp32 -> fp16 ----------------------------------------
__global__ void round_half(const float* __restrict__ src, __half* __restrict__ dst, int n)
{
    for (int i = blockIdx.x * blockDim.x + threadIdx.x; i * 4 < n;
         i += gridDim.x * blockDim.x) {
        float4 v = *reinterpret_cast<const float4*>(src + i * 4);
        *reinterpret_cast<__half2*>(dst + i * 4)     = __floats2half2_rn(v.x, v.y);
        *reinterpret_cast<__half2*>(dst + i * 4 + 2) = __floats2half2_rn(v.z, v.w);
    }
}

// ---------------- tiled fp16 transpose [L,D] -> [D,L] per batch --------------
__global__ void transposeH(const __half* __restrict__ src, __half* __restrict__ dst)
{
    __shared__ __half t[32][33];
    int b  = blockIdx.z;
    int d0 = blockIdx.x * 32, l0 = blockIdx.y * 32;
    int x = threadIdx.x, y0 = threadIdx.y;   // 32 x 8
#pragma unroll
    for (int i = 0; i < 4; i++) {
        int y = y0 + i * 8;
        t[y][x] = src[((long)b * LL + l0 + y) * DD + d0 + x];
    }
    __syncthreads();
#pragma unroll
    for (int i = 0; i < 4; i++) {
        int y = y0 + i * 8;
        dst[((long)b * DD + d0 + y) * LL + l0 + x] = t[x][y];
    }
}

// ---------------- masked softmax: fp32 scores in, fp16 out ------------------
__global__ void softmask_kernel(const float* __restrict__ S, __half* __restrict__ SH,
                                const float* __restrict__ mask)
{
    int gw   = (blockIdx.x * blockDim.x + threadIdx.x) >> 5;
    int lane = threadIdx.x & 31;
    if (gw >= BB * LL) return;
    int b = gw / LL;
    int l = gw - b * LL;
    const float* row = S + (long)gw * LL;
    __half* rowH = SH + (long)gw * LL;
    const float* mk = mask + (long)b * LL;

    float v[16];
    float mx = -1e30f;
#pragma unroll
    for (int t = 0; t < 16; t++) {
        v[t] = row[lane + t * 32];
        mx = fmaxf(mx, v[t]);
    }
#pragma unroll
    for (int o = 16; o; o >>= 1) mx = fmaxf(mx, __shfl_xor_sync(0xffffffffu, mx, o));

    float sum = 0.f;
#pragma unroll
    for (int t = 0; t < 16; t++) {
        float e = __expf(v[t] - mx) * mk[lane + t * 32];
        v[t] = e;
        sum += e;
    }
#pragma unroll
    for (int o = 16; o; o >>= 1) sum += __shfl_xor_sync(0xffffffffu, sum, o);

    float scale = mk[l] / (sum + 1e-10f);
#pragma unroll
    for (int t = 0; t < 16; t++) rowH[lane + t * 32] = __float2half_rn(v[t] * scale);
}

// ---------------- L2 normalize rows (fp16 in/out) ----------------------------
__global__ void l2norm_kernel(const __half* __restrict__ X, __half* __restrict__ Y)
{
    int gw   = (blockIdx.x * blockDim.x + threadIdx.x) >> 5;
    int lane = threadIdx.x & 31;
    if (gw >= BB * LL) return;
    const __half* x = X + (long)gw * DD;
    __half* y = Y + (long)gw * DD;
    float vv[24];
    float ss = 0.f;
#pragma unroll
    for (int t = 0; t < 24; t++) {
        vv[t] = __half2float(x[lane + t * 32]);
        ss += vv[t] * vv[t];
    }
#pragma unroll
    for (int o = 16; o; o >>= 1) ss += __shfl_xor_sync(0xffffffffu, ss, o);
    float scale = 1.f / fmaxf(sqrtf(ss), 1e-12f);
#pragma unroll
    for (int t = 0; t < 24; t++) y[lane + t * 32] = __float2half_rn(vv[t] * scale);
}

// ------- conv weight: W[h][o][i][tap] -> wtH[h][o][tap*768+i] fp16 -----------
__global__ void wtrans_kernel(const float* __restrict__ W)
{
    const long n = (long)HOPS * DD * 3 * DD;
    for (long i = blockIdx.x * (long)blockDim.x + threadIdx.x; i < n;
         i += (long)gridDim.x * blockDim.x) {
        long h   = i / ((long)DD * 3 * DD);
        long rem = i - h * (long)DD * 3 * DD;
        long o   = rem / (3 * DD);
        long k   = rem - o * 3 * DD;
        long tap = k / DD;
        long ii  = k - tap * DD;
        g_wtH[i] = __float2half_rn(W[((h * DD + o) * DD + ii) * 3 + tap]);
    }
}

// ------- pool W1 -> transposed fp16 [e][d] -----------------------------------
__global__ void w1trans_kernel(const float* __restrict__ W1)
{
    const int n = DD * DD;
    for (int i = blockIdx.x * blockDim.x + threadIdx.x; i < n;
         i += gridDim.x * blockDim.x) {
        int e = i / DD, d = i - e * DD;
        g_w1T[i] = __float2half_rn(W1[d * DD + e]);
    }
}

// ---------------- pooling tail ----------------------------------------------
__global__ void pool_finalize_kernel(const float* __restrict__ b2,
                                     float* __restrict__ out)
{
    int gw   = (blockIdx.x * blockDim.x + threadIdx.x) >> 5;
    int lane = threadIdx.x & 31;
    if (gw >= BB * LL) return;
    const __half* res = g_resultrH + (long)gw * NH * DD;

    float s[NH];
#pragma unroll
    for (int h = 0; h < NH; h++) {
        float p = (lane < 24) ? g_pp[(long)(gw * NH + h) * 24 + lane] : 0.f;
#pragma unroll
        for (int o = 16; o; o >>= 1) p += __shfl_xor_sync(0xffffffffu, p, o);
        s[h] = p + b2[0];
    }
    float mx = fmaxf(fmaxf(s[0], s[1]), fmaxf(s[2], s[3]));
    float e0 = __expf(s[0] - mx), e1 = __expf(s[1] - mx);
    float e2 = __expf(s[2] - mx), e3 = __expf(s[3] - mx);
    float inv = 1.f / (e0 + e1 + e2 + e3);
    e0 *= inv; e1 *= inv; e2 *= inv; e3 *= inv;

    float* o = out + (long)gw * DD;
#pragma unroll
    for (int t = 0; t < 24; t++) {
        int d = lane + t * 32;
        o[d] = e0 * __half2float(res[d]) + e1 * __half2float(res[DD + d])
             + e2 * __half2float(res[2 * DD + d]) + e3 * __half2float(res[3 * DD + d]);
    }
}

// ---------------- orchestration ---------------------------------------------
extern "C" void kernel_launch(void* const* d_in, const int* in_sizes, int n_in,
                              void* d_out, int out_size)
{
    (void)in_sizes; (void)n_in; (void)out_size;
    const float* inputs  = (const float*)d_in[0];
    const float* mask    = (const float*)d_in[1];
    const float* conv_w  = (const float*)d_in[2];
    const float* conv_b  = (const float*)d_in[3];
    const float* pool_w1 = (const float*)d_in[4];
    const float* pool_b1 = (const float*)d_in[5];
    const float* pool_w2 = (const float*)d_in[6];
    const float* pool_b2 = (const float*)d_in[7];
    float* out = (float*)d_out;

    __half *inrH, *inrT, *convrH0, *convrH1, *convrT, *nrm, *scoresH, *resultrH, *wtH, *w1T;
    float *scores, *pp;
    cudaGetSymbolAddress((void**)&inrH,     g_inrH);
    cudaGetSymbolAddress((void**)&inrT,     g_inrT);
    cudaGetSymbolAddress((void**)&convrH0,  g_convrH0);
    cudaGetSymbolAddress((void**)&convrH1,  g_convrH1);
    cudaGetSymbolAddress((void**)&convrT,   g_convrT);
    cudaGetSymbolAddress((void**)&nrm,      g_nrm);
    cudaGetSymbolAddress((void**)&scores,   g_scores);
    cudaGetSymbolAddress((void**)&scoresH,  g_scoresH);
    cudaGetSymbolAddress((void**)&resultrH, g_resultrH);
    cudaGetSymbolAddress((void**)&wtH,      g_wtH);
    cudaGetSymbolAddress((void**)&w1T,      g_w1T);
    cudaGetSymbolAddress((void**)&pp,       g_pp);

    constexpr int SMEM = 3 * (128 * 72 + 128 * 72) * 2;  // 110592 B
    cudaFuncSetAttribute(gemm_h<0, 0, 0>, cudaFuncAttributeMaxDynamicSharedMemorySize, SMEM);
    cudaFuncSetAttribute(gemm_h<0, 0, 1>, cudaFuncAttributeMaxDynamicSharedMemorySize, SMEM);
    cudaFuncSetAttribute(gemm_h<2, 1, 1>, cudaFuncAttributeMaxDynamicSharedMemorySize, SMEM);
    cudaFuncSetAttribute(gemm_h<2, 1, 2>, cudaFuncAttributeMaxDynamicSharedMemorySize, SMEM);
    cudaFuncSetAttribute(gemm_h<0, 3, 0>, cudaFuncAttributeMaxDynamicSharedMemorySize, SMEM);

    // setup: fp16 operands
    round_half<<<1024, 256>>>(inputs, inrH, BB * LL * DD);
    transposeH<<<dim3(DD / 32, LL / 32, BB), dim3(32, 8)>>>(inrH, inrT);
    wtrans_kernel<<<512, 256>>>(conv_w);
    w1trans_kernel<<<256, 256>>>(pool_w1);

    // ---- hop 0: raw similarity on inputs ----
    gemm_h<0, 0, 0><<<dim3(LL / 128, LL / 128, BB), 256, SMEM>>>(
        inrH, inrH, scores, nullptr, nullptr, nullptr, nullptr, nullptr,
        DD, DD, DD, LL, (long)LL * DD, (long)LL * DD, (long)LL * LL);
    softmask_kernel<<<BB * LL / 8, 256>>>(scores, scoresH, mask);
    gemm_h<0, 0, 1><<<dim3(DD / 128, LL / 128, BB), 256, SMEM>>>(
        scoresH, inrT, nullptr, resultrH, nullptr, nullptr, nullptr, nullptr,
        LL, LL, LL, NH * DD, (long)LL * LL, (long)DD * LL, (long)LL * NH * DD);

    // ---- hops 1..3 ----
    const __half* curH = inrH;   // token-major fp16 current sequence
    for (int h = 0; h < HOPS; h++) {
        __half* crDst = (h & 1) ? convrH1 : convrH0;
        if (h == HOPS - 1) {
            gemm_h<2, 1, 2><<<dim3(DD / 128, LL / 128, BB), 256, SMEM>>>(
                curH, wtH + (long)h * DD * 3 * DD, out, nullptr, crDst,
                conv_b + h * DD, nullptr, nullptr,
                3 * DD, 0, 3 * DD, DD, (long)LL * DD, 0L, (long)LL * DD);
        } else {
            gemm_h<2, 1, 1><<<dim3(DD / 128, LL / 128, BB), 256, SMEM>>>(
                curH, wtH + (long)h * DD * 3 * DD, nullptr, crDst, nullptr,
                conv_b + h * DD, nullptr, nullptr,
                3 * DD, 0, 3 * DD, DD, (long)LL * DD, 0L, (long)LL * DD);
        }
        l2norm_kernel<<<BB * LL / 8, 256>>>(crDst, nrm);
        gemm_h<0, 0, 0><<<dim3(LL / 128, LL / 128, BB), 256, SMEM>>>(
            nrm, nrm, scores, nullptr, nullptr, nullptr, nullptr, nullptr,
            DD, DD, DD, LL, (long)LL * DD, (long)LL * DD, (long)LL * LL);
        softmask_kernel<<<BB * LL / 8, 256>>>(scores, scoresH, mask);
        transposeH<<<dim3(DD / 32, LL / 32, BB), dim3(32, 8)>>>(crDst, convrT);
        gemm_h<0, 0, 1><<<dim3(DD / 128, LL / 128, BB), 256, SMEM>>>(
            scoresH, convrT, nullptr, resultrH + (long)(h + 1) * DD, nullptr,
            nullptr, nullptr, nullptr,
            LL, LL, LL, NH * DD, (long)LL * LL, (long)DD * LL, (long)LL * NH * DD);
        curH = crDst;
    }

    // pooling: fused tanh(result@W1+b1)·w2 partials
    gemm_h<0, 3, 0><<<dim3(DD / 128, (BB * LL * NH) / 128, 1), 256, SMEM>>>(
        resultrH, w1T, nullptr, nullptr, nullptr, pool_b1, pool_w2, pp,
        DD, DD, DD, DD, 0L, 0L, 0L);

    // output #2: weighted
    pool_finalize_kernel<<<BB * LL / 8, 256>>>(pool_b2, out + (long)BB * LL * DD);
}